// round 8
// baseline (speedup 1.0000x reference)
#include <cuda_runtime.h>
#include <cstdint>

#define B_ 4
#define L_ 2048
#define H_ 16
#define DH_ 64
#define DM_ 1024
#define N3_ 3072
#define BH_ (B_*H_)
#define OUT_ELEMS_ (B_*L_*DM_)   // 8388608

// Scratch (device globals: allocation-free per harness rules)
__device__ float g_qhi[BH_*L_*DH_];
__device__ float g_qlo[BH_*L_*DH_];
__device__ float g_khi[BH_*L_*DH_];
__device__ float g_klo[BH_*L_*DH_];
__device__ float g_v[BH_*L_*DH_];
__device__ float g_hout[B_*L_*DM_];
__device__ float g_rowsum[BH_*L_];

// tf32 hi/lo decompositions for the projections
__device__ float g_xhi[B_*L_*DM_];
__device__ float g_xlo[B_*L_*DM_];
__device__ float g_wqhi[N3_*DM_];    // [n][k] (transposed W_qkv)
__device__ float g_wqlo[N3_*DM_];
__device__ float g_wohi[DM_*DM_];    // [n][k] (transposed W_out)
__device__ float g_wolo[DM_*DM_];
__device__ float g_hhi[B_*L_*DM_];
__device__ float g_hlo[B_*L_*DM_];

// ---------------------------------------------------------------------------
// Helpers
// ---------------------------------------------------------------------------
__device__ __forceinline__ uint32_t smem_u32(const void* p) {
    uint32_t a;
    asm("{ .reg .u64 t; cvta.to.shared.u64 t, %1; cvt.u32.u64 %0, t; }"
        : "=r"(a) : "l"(p));
    return a;
}
__device__ __forceinline__ void cpa16(uint32_t dst, const float* src) {
    asm volatile("cp.async.cg.shared.global [%0], [%1], 16;" :: "r"(dst), "l"(src));
}
__device__ __forceinline__ float2 tf32split(float a) {
    uint32_t hb;
    asm("cvt.rna.tf32.f32 %0, %1;" : "=r"(hb) : "f"(a));
    float hi = __uint_as_float(hb);
    float lo = a - hi;
    uint32_t lb;
    asm("cvt.rna.tf32.f32 %0, %1;" : "=r"(lb) : "f"(lo));
    return make_float2(hi, __uint_as_float(lb));
}
// m16n8k8 tf32 MMA (baseline PTX, works on compute_103)
__device__ __forceinline__ void mma8(float c[4], const float a[4], const float b[2]) {
    asm volatile(
        "mma.sync.aligned.m16n8k8.row.col.f32.tf32.tf32.f32 "
        "{%0,%1,%2,%3}, {%4,%5,%6,%7}, {%8,%9}, {%0,%1,%2,%3};"
        : "+f"(c[0]), "+f"(c[1]), "+f"(c[2]), "+f"(c[3])
        : "r"(__float_as_uint(a[0])), "r"(__float_as_uint(a[1])),
          "r"(__float_as_uint(a[2])), "r"(__float_as_uint(a[3])),
          "r"(__float_as_uint(b[0])), "r"(__float_as_uint(b[1])));
}

// f32x2 packed FMA (AV loop)
__device__ __forceinline__ unsigned long long pk2(float x, float y) {
    unsigned long long r;
    asm("mov.b64 %0, {%1, %2};" : "=l"(r) : "f"(x), "f"(y));
    return r;
}
__device__ __forceinline__ float2 upk2(unsigned long long v) {
    float lo, hi;
    asm("mov.b64 {%0, %1}, %2;" : "=f"(lo), "=f"(hi) : "l"(v));
    return make_float2(lo, hi);
}
__device__ __forceinline__ void fma2(unsigned long long& d,
                                     unsigned long long a,
                                     unsigned long long b) {
    asm("fma.rn.f32x2 %0, %1, %2, %3;" : "=l"(d) : "l"(a), "l"(b), "l"(d));
}

// ---------------------------------------------------------------------------
// Decomposition kernels
// ---------------------------------------------------------------------------
__global__ __launch_bounds__(256) void decomp_kernel(
    const float* __restrict__ src, float* __restrict__ hi, float* __restrict__ lo)
{
    int i = blockIdx.x * 256 + threadIdx.x;
    float4 v = ((const float4*)src)[i];
    float2 sx = tf32split(v.x), sy = tf32split(v.y);
    float2 sz = tf32split(v.z), sw = tf32split(v.w);
    ((float4*)hi)[i] = make_float4(sx.x, sy.x, sz.x, sw.x);
    ((float4*)lo)[i] = make_float4(sx.y, sy.y, sz.y, sw.y);
}

// W[k][n] -> hi/lo [n][k]
__global__ __launch_bounds__(256) void decomp_t_kernel(
    const float* __restrict__ src, float* __restrict__ dhi, float* __restrict__ dlo,
    int K, int N)
{
    __shared__ float t[32][33];
    int k0 = blockIdx.y * 32, n0 = blockIdx.x * 32;
    int r = threadIdx.x >> 3;
    int c4 = (threadIdx.x & 7) * 4;
    float4 v = *(const float4*)(src + (size_t)(k0 + r) * N + n0 + c4);
    t[r][c4 + 0] = v.x; t[r][c4 + 1] = v.y; t[r][c4 + 2] = v.z; t[r][c4 + 3] = v.w;
    __syncthreads();
    float2 s0 = tf32split(t[c4 + 0][r]);
    float2 s1 = tf32split(t[c4 + 1][r]);
    float2 s2 = tf32split(t[c4 + 2][r]);
    float2 s3 = tf32split(t[c4 + 3][r]);
    *(float4*)(dhi + (size_t)(n0 + r) * K + k0 + c4) =
        make_float4(s0.x, s1.x, s2.x, s3.x);
    *(float4*)(dlo + (size_t)(n0 + r) * K + k0 + c4) =
        make_float4(s0.y, s1.y, s2.y, s3.y);
}

// ---------------------------------------------------------------------------
// mma.sync tf32 3x GEMM (structure proven in R7).
// MODE 0: out projection  (C -> Cout[m][n] + bias)
// MODE 1: qkv projection  (q,k written as tf32 hi/lo splits; v plain)
// ---------------------------------------------------------------------------
#define ARR_F 4608              // 128*36 floats
#define STAGE_F (4 * ARR_F)     // 18432 floats
#define GEMM_SMEM_BYTES (3 * STAGE_F * 4)   // 221184

template <int MODE>
__global__ __launch_bounds__(256, 1) void gemm_mma_kernel(
    const float* __restrict__ Ahi, const float* __restrict__ Alo,
    const float* __restrict__ Bhi, const float* __restrict__ Blo,
    const float* __restrict__ bias, float* __restrict__ Cout)
{
    extern __shared__ float gsm[];
    const uint32_t sbase = smem_u32(gsm);
    const int tid = threadIdx.x;
    const int wid = tid >> 5;
    const int lane = tid & 31;
    const int grp = lane >> 2;      // 0..7
    const int tg = lane & 3;        // 0..3
    const int n0 = blockIdx.x * 128;
    const int m0 = blockIdx.y * 128;

    const int lrow = tid >> 1;
    const int lg4 = (tid & 1) * 4;

    const float* srcA_hi = Ahi + (size_t)(m0 + lrow) * DM_ + lg4 * 4;
    const float* srcA_lo = Alo + (size_t)(m0 + lrow) * DM_ + lg4 * 4;
    const float* srcB_hi = Bhi + (size_t)(n0 + lrow) * DM_ + lg4 * 4;
    const float* srcB_lo = Blo + (size_t)(n0 + lrow) * DM_ + lg4 * 4;

    auto load_chunk = [&](int c) {
        if (c < 32) {
            const int st = c % 3;
            const uint32_t sb = sbase + (st * STAGE_F) * 4;
            const uint32_t dbase = sb + (lrow * 36 + lg4 * 4) * 4;
            const int k0 = c * 32;
#pragma unroll
            for (int j = 0; j < 4; j++) {
                cpa16(dbase + 0 * ARR_F * 4 + j * 16, srcA_hi + k0 + j * 4);
                cpa16(dbase + 1 * ARR_F * 4 + j * 16, srcA_lo + k0 + j * 4);
                cpa16(dbase + 2 * ARR_F * 4 + j * 16, srcB_hi + k0 + j * 4);
                cpa16(dbase + 3 * ARR_F * 4 + j * 16, srcB_lo + k0 + j * 4);
            }
        }
        asm volatile("cp.async.commit_group;" ::: "memory");
    };

    const int wm = wid & 1;
    const int wn = wid >> 1;

    float acc[4][4][4];
#pragma unroll
    for (int mf = 0; mf < 4; mf++)
#pragma unroll
        for (int nf = 0; nf < 4; nf++)
#pragma unroll
            for (int e = 0; e < 4; e++) acc[mf][nf][e] = 0.f;

    load_chunk(0);
    load_chunk(1);

    for (int c = 0; c < 32; c++) {
        asm volatile("cp.async.wait_group 1;" ::: "memory");
        __syncthreads();

        const float* sb = gsm + (c % 3) * STAGE_F;
        const float* sAhi = sb;
        const float* sAlo = sb + ARR_F;
        const float* sBhi = sb + 2 * ARR_F;
        const float* sBlo = sb + 3 * ARR_F;

#pragma unroll
        for (int k8 = 0; k8 < 4; k8++) {
            const int kk = k8 * 8;
            float aH[4][4], aL[4][4];
#pragma unroll
            for (int mf = 0; mf < 4; mf++) {
                int mr = wm * 64 + mf * 16 + grp;
                aH[mf][0] = sAhi[(mr) * 36 + kk + tg];
                aH[mf][1] = sAhi[(mr + 8) * 36 + kk + tg];
                aH[mf][2] = sAhi[(mr) * 36 + kk + tg + 4];
                aH[mf][3] = sAhi[(mr + 8) * 36 + kk + tg + 4];
                aL[mf][0] = sAlo[(mr) * 36 + kk + tg];
                aL[mf][1] = sAlo[(mr + 8) * 36 + kk + tg];
                aL[mf][2] = sAlo[(mr) * 36 + kk + tg + 4];
                aL[mf][3] = sAlo[(mr + 8) * 36 + kk + tg + 4];
            }
            float bH[4][2], bL[4][2];
#pragma unroll
            for (int nf = 0; nf < 4; nf++) {
                int nr = wn * 32 + nf * 8 + grp;
                bH[nf][0] = sBhi[nr * 36 + kk + tg];
                bH[nf][1] = sBhi[nr * 36 + kk + tg + 4];
                bL[nf][0] = sBlo[nr * 36 + kk + tg];
                bL[nf][1] = sBlo[nr * 36 + kk + tg + 4];
            }
#pragma unroll
            for (int mf = 0; mf < 4; mf++)
#pragma unroll
                for (int nf = 0; nf < 4; nf++) {
                    mma8(acc[mf][nf], aH[mf], bH[nf]);
                    mma8(acc[mf][nf], aH[mf], bL[nf]);
                    mma8(acc[mf][nf], aL[mf], bH[nf]);
                }
        }
        __syncthreads();
        load_chunk(c + 2);
    }

#pragma unroll
    for (int mf = 0; mf < 4; mf++) {
#pragma unroll
        for (int nf = 0; nf < 4; nf++) {
            int m = m0 + wm * 64 + mf * 16 + grp;
            int n = n0 + wn * 32 + nf * 8 + tg * 2;
            float b0 = __ldg(bias + n), b1 = __ldg(bias + n + 1);
            float2 v0 = make_float2(acc[mf][nf][0] + b0, acc[mf][nf][1] + b1);
            float2 v1 = make_float2(acc[mf][nf][2] + b0, acc[mf][nf][3] + b1);
            if (MODE == 0) {
                *(float2*)(Cout + (size_t)m * DM_ + n) = v0;
                *(float2*)(Cout + (size_t)(m + 8) * DM_ + n) = v1;
            } else {
                int mat = n >> 10;
                int cc = n & 1023;
                int h = cc >> 6, dd = cc & 63;
                int bidx = m >> 11;
                int l = m & 2047;
                size_t i0 = (((size_t)(bidx * H_ + h)) * L_ + l) * DH_ + dd;
                size_t i1 = (((size_t)(bidx * H_ + h)) * L_ + l + 8) * DH_ + dd;
                if (mat == 2) {
                    *(float2*)(g_v + i0) = v0;
                    *(float2*)(g_v + i1) = v1;
                } else {
                    float* dh = (mat == 0) ? g_qhi : g_khi;
                    float* dl = (mat == 0) ? g_qlo : g_klo;
                    float2 sx = tf32split(v0.x), sy = tf32split(v0.y);
                    *(float2*)(dh + i0) = make_float2(sx.x, sy.x);
                    *(float2*)(dl + i0) = make_float2(sx.y, sy.y);
                    sx = tf32split(v1.x); sy = tf32split(v1.y);
                    *(float2*)(dh + i1) = make_float2(sx.x, sy.x);
                    *(float2*)(dl + i1) = make_float2(sx.y, sy.y);
                }
            }
        }
    }
}

// ---------------------------------------------------------------------------
// Attention: per CTA 128 q-rows; key tiles of 128.
//  - scores via m16n8k8 3xTF32 (Q/K pre-split hi/lo by the qkv gemm)
//  - exp + rowsum in fragment layout; unnormalized e -> gmem
//  - AV via FFMA2 reading e back through L1 (R4-proven)
// smem floats: sQh[128*68], sQl, sKh, sKl, sV (each 8704), srow[128]
// ---------------------------------------------------------------------------
#define QK_STRIDE 68
#define TILE_F (128 * QK_STRIDE)   // 8704
#define ATTN_SMEM_BYTES ((5 * TILE_F + 128) * 4)   // 174592

__global__ __launch_bounds__(256, 1) void attn_kernel(float* __restrict__ attn_out)
{
    extern __shared__ float sm[];
    float* sQh = sm;
    float* sQl = sm + TILE_F;
    float* sKh = sm + 2 * TILE_F;
    float* sKl = sm + 3 * TILE_F;
    float* sV  = sm + 4 * TILE_F;
    float* srow = sm + 5 * TILE_F;
    const uint32_t sb = smem_u32(sm);

    const int tid = threadIdx.x;
    const int wid = tid >> 5;
    const int lane = tid & 31;
    const int grp = lane >> 2;
    const int tg = lane & 3;
    const int wm = wid & 1;         // m-half (64 q rows)
    const int wn = wid >> 1;        // key-quarter (32 keys)

    const int bh = blockIdx.y;
    const int q0 = blockIdx.x * 128;
    const size_t base = (size_t)bh * L_ * DH_;
    float* attn = attn_out + (size_t)bh * L_ * L_;

    if (tid < 128) srow[tid] = 0.f;

    // load Q hi/lo (one-time)
    {
        int qr = tid >> 1;
        int qc = (tid & 1) * 32;
        const float* qh = g_qhi + base + (size_t)(q0 + qr) * DH_ + qc;
        const float* ql = g_qlo + base + (size_t)(q0 + qr) * DH_ + qc;
        uint32_t dh = sb + (qr * QK_STRIDE + qc) * 4;
        uint32_t dl = dh + TILE_F * 4;
#pragma unroll
        for (int j = 0; j < 8; j++) {
            cpa16(dh + j * 16, qh + j * 4);
            cpa16(dl + j * 16, ql + j * 4);
        }
        asm volatile("cp.async.commit_group;" ::: "memory");
        asm volatile("cp.async.wait_group 0;" ::: "memory");
    }
    __syncthreads();

    float rs[8];
#pragma unroll
    for (int i = 0; i < 8; i++) rs[i] = 0.f;

    // AV thread mapping (R4-proven)
    const int ty = tid >> 4;        // 0..15 : rows ty*8..+7
    const int tx = tid & 15;        // 0..15 : dims tx*4..+3
    unsigned long long oacc[8][2];
#pragma unroll
    for (int i = 0; i < 8; i++) { oacc[i][0] = 0ull; oacc[i][1] = 0ull; }

    for (int kt = 0; kt < L_ / 128; kt++) {
        const int k0g = kt * 128;
        __syncthreads();   // previous tile's consumers done with sK/sV

        // load K hi/lo + V for this tile
        {
            int kr = tid >> 1;
            int kc = (tid & 1) * 32;
            const float* kh = g_khi + base + (size_t)(k0g + kr) * DH_ + kc;
            const float* kl = g_klo + base + (size_t)(k0g + kr) * DH_ + kc;
            const float* vv = g_v  + base + (size_t)(k0g + kr) * DH_ + kc;
            uint32_t dh = sb + (2 * TILE_F + kr * QK_STRIDE + kc) * 4;
#pragma unroll
            for (int j = 0; j < 8; j++) {
                cpa16(dh + j * 16, kh + j * 4);
                cpa16(dh + TILE_F * 4 + j * 16, kl + j * 4);
                cpa16(dh + 2 * TILE_F * 4 + j * 16, vv + j * 4);
            }
            asm volatile("cp.async.commit_group;" ::: "memory");
            asm volatile("cp.async.wait_group 0;" ::: "memory");
        }
        __syncthreads();

        // scores: 3xTF32 mma, warp tile 64x32
        float acc[4][4][4];
#pragma unroll
        for (int mf = 0; mf < 4; mf++)
#pragma unroll
            for (int nf = 0; nf < 4; nf++)
#pragma unroll
                for (int e = 0; e < 4; e++) acc[mf][nf][e] = 0.f;

#pragma unroll
        for (int k8 = 0; k8 < 8; k8++) {
            const int kk = k8 * 8;
            float aH[4][4], aL[4][4];
#pragma unroll
            for (int mf = 0; mf < 4; mf++) {
                int mr = wm * 64 + mf * 16 + grp;
                aH[mf][0] = sQh[(mr) * QK_STRIDE + kk + tg];
                aH[mf][1] = sQh[(mr + 8) * QK_STRIDE + kk + tg];
                aH[mf][2] = sQh[(mr) * QK_STRIDE + kk + tg + 4];
                aH[mf][3] = sQh[(mr + 8) * QK_STRIDE + kk + tg + 4];
                aL[mf][0] = sQl[(mr) * QK_STRIDE + kk + tg];
                aL[mf][1] = sQl[(mr + 8) * QK_STRIDE + kk + tg];
                aL[mf][2] = sQl[(mr) * QK_STRIDE + kk + tg + 4];
                aL[mf][3] = sQl[(mr + 8) * QK_STRIDE + kk + tg + 4];
            }
            float bH[4][2], bL[4][2];
#pragma unroll
            for (int nf = 0; nf < 4; nf++) {
                int nr = wn * 32 + nf * 8 + grp;
                bH[nf][0] = sKh[nr * QK_STRIDE + kk + tg];
                bH[nf][1] = sKh[nr * QK_STRIDE + kk + tg + 4];
                bL[nf][0] = sKl[nr * QK_STRIDE + kk + tg];
                bL[nf][1] = sKl[nr * QK_STRIDE + kk + tg + 4];
            }
#pragma unroll
            for (int mf = 0; mf < 4; mf++)
#pragma unroll
                for (int nf = 0; nf < 4; nf++) {
                    mma8(acc[mf][nf], aH[mf], bH[nf]);
                    mma8(acc[mf][nf], aH[mf], bL[nf]);
                    mma8(acc[mf][nf], aL[mf], bH[nf]);
                }
        }

        // exp + rowsum partials + store unnormalized e
#pragma unroll
        for (int mf = 0; mf < 4; mf++) {
            int r0 = q0 + wm * 64 + mf * 16 + grp;
#pragma unroll
            for (int nf = 0; nf < 4; nf++) {
                int n = k0g + wn * 32 + nf * 8 + tg * 2;
                float e0 = __expf(acc[mf][nf][0] * 0.125f);
                float e1 = __expf(acc[mf][nf][1] * 0.125f);
                float e2 = __expf(acc[mf][nf][2] * 0.125f);
                float e3 = __expf(acc[mf][nf][3] * 0.125f);
                rs[mf * 2 + 0] += e0 + e1;
                rs[mf * 2 + 1] += e2 + e3;
                *(float2*)(attn + (size_t)r0 * L_ + n) = make_float2(e0, e1);
                *(float2*)(attn + (size_t)(r0 + 8) * L_ + n) = make_float2(e2, e3);
            }
        }
        __syncthreads();   // e visible CTA-wide

        // AV: FFMA2, P read back from gmem (L1/L2 hot)
#pragma unroll 2
        for (int k = 0; k < 128; k += 4) {
            float4 pr[8];
#pragma unroll
            for (int i = 0; i < 8; i++)
                pr[i] = *(const float4*)(attn + (size_t)(q0 + ty * 8 + i) * L_ + k0g + k);
#pragma unroll
            for (int t = 0; t < 4; t++) {
                ulonglong2 vt = *(const ulonglong2*)&sV[(k + t) * QK_STRIDE + tx * 4];
#pragma unroll
                for (int i = 0; i < 8; i++) {
                    float pv = (t == 0) ? pr[i].x : (t == 1) ? pr[i].y
                             : (t == 2) ? pr[i].z : pr[i].w;
                    unsigned long long pp = pk2(pv, pv);
                    fma2(oacc[i][0], pp, vt.x);
                    fma2(oacc[i][1], pp, vt.y);
                }
            }
        }
    }

    // rowsum: reduce over tg-quad, then cross-warp via smem atomics
#pragma unroll
    for (int i = 0; i < 8; i++) {
        rs[i] += __shfl_xor_sync(0xffffffffu, rs[i], 1);
        rs[i] += __shfl_xor_sync(0xffffffffu, rs[i], 2);
    }
    if (tg == 0) {
#pragma unroll
        for (int mf = 0; mf < 4; mf++) {
            atomicAdd(&srow[wm * 64 + mf * 16 + grp], rs[mf * 2 + 0]);
            atomicAdd(&srow[wm * 64 + mf * 16 + grp + 8], rs[mf * 2 + 1]);
        }
    }
    __syncthreads();

    const int bidx = bh >> 4;
    const int h = bh & 15;
#pragma unroll
    for (int i = 0; i < 8; i++) {
        float inv = 1.f / srow[ty * 8 + i];
        float2 u0 = upk2(oacc[i][0]);
        float2 u1 = upk2(oacc[i][1]);
        float4 o = make_float4(u0.x * inv, u0.y * inv, u1.x * inv, u1.y * inv);
        *(float4*)(g_hout + ((size_t)(bidx * L_) + q0 + ty * 8 + i) * DM_
                   + h * DH_ + tx * 4) = o;
    }
    if (tid < 128) g_rowsum[(size_t)bh * L_ + q0 + tid] = srow[tid];
}

// ---------------------------------------------------------------------------
// Rescale attn rows by 1/rowsum (bandwidth-bound standalone pass)
// ---------------------------------------------------------------------------
__global__ __launch_bounds__(256) void scale_attn_kernel(float* __restrict__ attn)
{
    size_t row = blockIdx.x;
    float inv = 1.f / g_rowsum[row];
    float4* p = (float4*)(attn + row * L_);
    int tid = threadIdx.x;
#pragma unroll
    for (int i = 0; i < L_ / 4 / 256; i++) {
        float4 v = p[tid + i * 256];
        v.x *= inv; v.y *= inv; v.z *= inv; v.w *= inv;
        p[tid + i * 256] = v;
    }
}

// ---------------------------------------------------------------------------
extern "C" void kernel_launch(void* const* d_in, const int* in_sizes, int n_in,
                              void* d_out, int out_size)
{
    (void)in_sizes; (void)n_in; (void)out_size;
    const float* x    = (const float*)d_in[0];
    const float* Wqkv = (const float*)d_in[1];
    const float* bqkv = (const float*)d_in[2];
    const float* Wout = (const float*)d_in[3];
    const float* bout = (const float*)d_in[4];
    float* out  = (float*)d_out;
    float* attn = out + OUT_ELEMS_;

    static int attr_done = 0;
    if (!attr_done) {
        cudaFuncSetAttribute(attn_kernel,
            cudaFuncAttributeMaxDynamicSharedMemorySize, ATTN_SMEM_BYTES);
        cudaFuncSetAttribute(gemm_mma_kernel<0>,
            cudaFuncAttributeMaxDynamicSharedMemorySize, GEMM_SMEM_BYTES);
        cudaFuncSetAttribute(gemm_mma_kernel<1>,
            cudaFuncAttributeMaxDynamicSharedMemorySize, GEMM_SMEM_BYTES);
        attr_done = 1;
    }

    float *xhi, *xlo, *wqhi, *wqlo, *wohi, *wolo, *hhi, *hlo, *hout;
    cudaGetSymbolAddress((void**)&xhi,  g_xhi);
    cudaGetSymbolAddress((void**)&xlo,  g_xlo);
    cudaGetSymbolAddress((void**)&wqhi, g_wqhi);
    cudaGetSymbolAddress((void**)&wqlo, g_wqlo);
    cudaGetSymbolAddress((void**)&wohi, g_wohi);
    cudaGetSymbolAddress((void**)&wolo, g_wolo);
    cudaGetSymbolAddress((void**)&hhi,  g_hhi);
    cudaGetSymbolAddress((void**)&hlo,  g_hlo);
    cudaGetSymbolAddress((void**)&hout, g_hout);

    // operand decompositions
    decomp_kernel<<<OUT_ELEMS_ / 4 / 256, 256>>>(x, xhi, xlo);
    decomp_t_kernel<<<dim3(N3_ / 32, DM_ / 32), 256>>>(Wqkv, wqhi, wqlo, DM_, N3_);
    decomp_t_kernel<<<dim3(DM_ / 32, DM_ / 32), 256>>>(Wout, wohi, wolo, DM_, DM_);

    // QKV projection (q,k written pre-split into tf32 hi/lo)
    gemm_mma_kernel<1><<<dim3(N3_ / 128, (B_ * L_) / 128), 256, GEMM_SMEM_BYTES>>>(
        xhi, xlo, wqhi, wqlo, bqkv, nullptr);

    // attention (QK on tensor pipe) + standalone rescale
    attn_kernel<<<dim3(L_ / 128, BH_), 256, ATTN_SMEM_BYTES>>>(attn);
    scale_attn_kernel<<<dim3(BH_ * L_), 256>>>(attn);

    // out projection
    decomp_kernel<<<OUT_ELEMS_ / 4 / 256, 256>>>(hout, hhi, hlo);
    gemm_mma_kernel<0><<<dim3(DM_ / 128, (B_ * L_) / 128), 256, GEMM_SMEM_BYTES>>>(
        hhi, hlo, wohi, wolo, bout, out);
}

// round 9
// speedup vs baseline: 1.1944x; 1.1944x over previous
#include <cuda_runtime.h>
#include <cstdint>

#define B_ 4
#define L_ 2048
#define H_ 16
#define DH_ 64
#define DM_ 1024
#define N3_ 3072
#define BH_ (B_*H_)
#define OUT_ELEMS_ (B_*L_*DM_)   // 8388608

// Scratch (device globals: allocation-free per harness rules)
__device__ float g_q[BH_*L_*DH_];
__device__ float g_k[BH_*L_*DH_];
__device__ float g_v[BH_*L_*DH_];
__device__ float g_hout[B_*L_*DM_];

// tf32 hi/lo decompositions
__device__ float g_xhi[B_*L_*DM_];
__device__ float g_xlo[B_*L_*DM_];
__device__ float g_wqhi[N3_*DM_];    // [n][k] (transposed W_qkv)
__device__ float g_wqlo[N3_*DM_];
__device__ float g_wohi[DM_*DM_];    // [n][k] (transposed W_out)
__device__ float g_wolo[DM_*DM_];
__device__ float g_hhi[B_*L_*DM_];
__device__ float g_hlo[B_*L_*DM_];

// ---------------------------------------------------------------------------
// Helpers
// ---------------------------------------------------------------------------
__device__ __forceinline__ uint32_t smem_u32(const void* p) {
    uint32_t a;
    asm("{ .reg .u64 t; cvta.to.shared.u64 t, %1; cvt.u32.u64 %0, t; }"
        : "=r"(a) : "l"(p));
    return a;
}
__device__ __forceinline__ void cpa16(uint32_t dst, const float* src) {
    asm volatile("cp.async.cg.shared.global [%0], [%1], 16;" :: "r"(dst), "l"(src));
}
__device__ __forceinline__ float2 tf32split(float a) {
    uint32_t hb;
    asm("cvt.rna.tf32.f32 %0, %1;" : "=r"(hb) : "f"(a));
    float hi = __uint_as_float(hb);
    float lo = a - hi;
    uint32_t lb;
    asm("cvt.rna.tf32.f32 %0, %1;" : "=r"(lb) : "f"(lo));
    return make_float2(hi, __uint_as_float(lb));
}
// m16n8k8 tf32 MMA (baseline PTX, works on compute_103)
__device__ __forceinline__ void mma8(float c[4], const float a[4], const float b[2]) {
    asm volatile(
        "mma.sync.aligned.m16n8k8.row.col.f32.tf32.tf32.f32 "
        "{%0,%1,%2,%3}, {%4,%5,%6,%7}, {%8,%9}, {%0,%1,%2,%3};"
        : "+f"(c[0]), "+f"(c[1]), "+f"(c[2]), "+f"(c[3])
        : "r"(__float_as_uint(a[0])), "r"(__float_as_uint(a[1])),
          "r"(__float_as_uint(a[2])), "r"(__float_as_uint(a[3])),
          "r"(__float_as_uint(b[0])), "r"(__float_as_uint(b[1])));
}

// f32x2 packed FMA (attn kernel)
__device__ __forceinline__ unsigned long long pk2(float x, float y) {
    unsigned long long r;
    asm("mov.b64 %0, {%1, %2};" : "=l"(r) : "f"(x), "f"(y));
    return r;
}
__device__ __forceinline__ float2 upk2(unsigned long long v) {
    float lo, hi;
    asm("mov.b64 {%0, %1}, %2;" : "=f"(lo), "=f"(hi) : "l"(v));
    return make_float2(lo, hi);
}
__device__ __forceinline__ void fma2(unsigned long long& d,
                                     unsigned long long a,
                                     unsigned long long b) {
    asm("fma.rn.f32x2 %0, %1, %2, %3;" : "=l"(d) : "l"(a), "l"(b), "l"(d));
}

// ---------------------------------------------------------------------------
// Decomposition kernels
// ---------------------------------------------------------------------------
__global__ __launch_bounds__(256) void decomp_kernel(
    const float* __restrict__ src, float* __restrict__ hi, float* __restrict__ lo)
{
    int i = blockIdx.x * 256 + threadIdx.x;
    float4 v = ((const float4*)src)[i];
    float2 sx = tf32split(v.x), sy = tf32split(v.y);
    float2 sz = tf32split(v.z), sw = tf32split(v.w);
    ((float4*)hi)[i] = make_float4(sx.x, sy.x, sz.x, sw.x);
    ((float4*)lo)[i] = make_float4(sx.y, sy.y, sz.y, sw.y);
}

// W[k][n] -> hi/lo [n][k]
__global__ __launch_bounds__(256) void decomp_t_kernel(
    const float* __restrict__ src, float* __restrict__ dhi, float* __restrict__ dlo,
    int K, int N)
{
    __shared__ float t[32][33];
    int k0 = blockIdx.y * 32, n0 = blockIdx.x * 32;
    int r = threadIdx.x >> 3;
    int c4 = (threadIdx.x & 7) * 4;
    float4 v = *(const float4*)(src + (size_t)(k0 + r) * N + n0 + c4);
    t[r][c4 + 0] = v.x; t[r][c4 + 1] = v.y; t[r][c4 + 2] = v.z; t[r][c4 + 3] = v.w;
    __syncthreads();
    float2 s0 = tf32split(t[c4 + 0][r]);
    float2 s1 = tf32split(t[c4 + 1][r]);
    float2 s2 = tf32split(t[c4 + 2][r]);
    float2 s3 = tf32split(t[c4 + 3][r]);
    *(float4*)(dhi + (size_t)(n0 + r) * K + k0 + c4) =
        make_float4(s0.x, s1.x, s2.x, s3.x);
    *(float4*)(dlo + (size_t)(n0 + r) * K + k0 + c4) =
        make_float4(s0.y, s1.y, s2.y, s3.y);
}

// ---------------------------------------------------------------------------
// mma.sync tf32 3x GEMM (R7-proven).
// MODE 0: out projection  (C -> Cout[m][n] + bias)
// MODE 1: qkv projection  (C + bias scattered into g_q/g_k/g_v)
// ---------------------------------------------------------------------------
#define ARR_F 4608              // 128*36 floats
#define STAGE_F (4 * ARR_F)     // 18432 floats
#define GEMM_SMEM_BYTES (3 * STAGE_F * 4)   // 221184

template <int MODE>
__global__ __launch_bounds__(256, 1) void gemm_mma_kernel(
    const float* __restrict__ Ahi, const float* __restrict__ Alo,
    const float* __restrict__ Bhi, const float* __restrict__ Blo,
    const float* __restrict__ bias, float* __restrict__ Cout)
{
    extern __shared__ float gsm[];
    const uint32_t sbase = smem_u32(gsm);
    const int tid = threadIdx.x;
    const int wid = tid >> 5;
    const int lane = tid & 31;
    const int grp = lane >> 2;      // 0..7
    const int tg = lane & 3;        // 0..3
    const int n0 = blockIdx.x * 128;
    const int m0 = blockIdx.y * 128;

    const int lrow = tid >> 1;
    const int lg4 = (tid & 1) * 4;

    const float* srcA_hi = Ahi + (size_t)(m0 + lrow) * DM_ + lg4 * 4;
    const float* srcA_lo = Alo + (size_t)(m0 + lrow) * DM_ + lg4 * 4;
    const float* srcB_hi = Bhi + (size_t)(n0 + lrow) * DM_ + lg4 * 4;
    const float* srcB_lo = Blo + (size_t)(n0 + lrow) * DM_ + lg4 * 4;

    auto load_chunk = [&](int c) {
        if (c < 32) {
            const int st = c % 3;
            const uint32_t sb = sbase + (st * STAGE_F) * 4;
            const uint32_t dbase = sb + (lrow * 36 + lg4 * 4) * 4;
            const int k0 = c * 32;
#pragma unroll
            for (int j = 0; j < 4; j++) {
                cpa16(dbase + 0 * ARR_F * 4 + j * 16, srcA_hi + k0 + j * 4);
                cpa16(dbase + 1 * ARR_F * 4 + j * 16, srcA_lo + k0 + j * 4);
                cpa16(dbase + 2 * ARR_F * 4 + j * 16, srcB_hi + k0 + j * 4);
                cpa16(dbase + 3 * ARR_F * 4 + j * 16, srcB_lo + k0 + j * 4);
            }
        }
        asm volatile("cp.async.commit_group;" ::: "memory");
    };

    const int wm = wid & 1;
    const int wn = wid >> 1;

    float acc[4][4][4];
#pragma unroll
    for (int mf = 0; mf < 4; mf++)
#pragma unroll
        for (int nf = 0; nf < 4; nf++)
#pragma unroll
            for (int e = 0; e < 4; e++) acc[mf][nf][e] = 0.f;

    load_chunk(0);
    load_chunk(1);

    for (int c = 0; c < 32; c++) {
        asm volatile("cp.async.wait_group 1;" ::: "memory");
        __syncthreads();

        const float* sb = gsm + (c % 3) * STAGE_F;
        const float* sAhi = sb;
        const float* sAlo = sb + ARR_F;
        const float* sBhi = sb + 2 * ARR_F;
        const float* sBlo = sb + 3 * ARR_F;

#pragma unroll
        for (int k8 = 0; k8 < 4; k8++) {
            const int kk = k8 * 8;
            float aH[4][4], aL[4][4];
#pragma unroll
            for (int mf = 0; mf < 4; mf++) {
                int mr = wm * 64 + mf * 16 + grp;
                aH[mf][0] = sAhi[(mr) * 36 + kk + tg];
                aH[mf][1] = sAhi[(mr + 8) * 36 + kk + tg];
                aH[mf][2] = sAhi[(mr) * 36 + kk + tg + 4];
                aH[mf][3] = sAhi[(mr + 8) * 36 + kk + tg + 4];
                aL[mf][0] = sAlo[(mr) * 36 + kk + tg];
                aL[mf][1] = sAlo[(mr + 8) * 36 + kk + tg];
                aL[mf][2] = sAlo[(mr) * 36 + kk + tg + 4];
                aL[mf][3] = sAlo[(mr + 8) * 36 + kk + tg + 4];
            }
            float bH[4][2], bL[4][2];
#pragma unroll
            for (int nf = 0; nf < 4; nf++) {
                int nr = wn * 32 + nf * 8 + grp;
                bH[nf][0] = sBhi[nr * 36 + kk + tg];
                bH[nf][1] = sBhi[nr * 36 + kk + tg + 4];
                bL[nf][0] = sBlo[nr * 36 + kk + tg];
                bL[nf][1] = sBlo[nr * 36 + kk + tg + 4];
            }
#pragma unroll
            for (int mf = 0; mf < 4; mf++)
#pragma unroll
                for (int nf = 0; nf < 4; nf++) {
                    mma8(acc[mf][nf], aH[mf], bH[nf]);
                    mma8(acc[mf][nf], aH[mf], bL[nf]);
                    mma8(acc[mf][nf], aL[mf], bH[nf]);
                }
        }
        __syncthreads();
        load_chunk(c + 2);
    }

#pragma unroll
    for (int mf = 0; mf < 4; mf++) {
#pragma unroll
        for (int nf = 0; nf < 4; nf++) {
            int m = m0 + wm * 64 + mf * 16 + grp;
            int n = n0 + wn * 32 + nf * 8 + tg * 2;
            float b0 = __ldg(bias + n), b1 = __ldg(bias + n + 1);
            float2 v0 = make_float2(acc[mf][nf][0] + b0, acc[mf][nf][1] + b1);
            float2 v1 = make_float2(acc[mf][nf][2] + b0, acc[mf][nf][3] + b1);
            if (MODE == 0) {
                *(float2*)(Cout + (size_t)m * DM_ + n) = v0;
                *(float2*)(Cout + (size_t)(m + 8) * DM_ + n) = v1;
            } else {
                int mat = n >> 10;
                int cc = n & 1023;
                int h = cc >> 6, dd = cc & 63;
                float* dst = (mat == 0) ? g_q : (mat == 1) ? g_k : g_v;
                int bidx = m >> 11;
                int l = m & 2047;
                *(float2*)(dst + (((size_t)(bidx * H_ + h)) * L_ + l) * DH_ + dd) = v0;
                *(float2*)(dst + (((size_t)(bidx * H_ + h)) * L_ + l + 8) * DH_ + dd) = v1;
            }
        }
    }
}

// ---------------------------------------------------------------------------
// Fused attention: 128 q-rows/CTA, 64-key tiles, FFMA2 score + AV.
// NEW vs R7: P staged in smem (sP) -- AV reads LDS (broadcast, conflict-free)
// instead of re-reading e from gmem through L1. e gmem store is
// fire-and-forget. Fused rescale of this CTA's rows at the end (R7-proven).
// smem floats: sqT[64][132]=8448, skT[64][68]=4352, sv[64][68]=4352,
//              sP[128][68]=8704, srow[128]  -> 25984 floats = 103936 B, occ 2
// ---------------------------------------------------------------------------
#define SQT_F 8448
#define SKT_F 4352
#define SV_F  4352
#define SP_F  8704
#define ATTN_SMEM_FLOATS (SQT_F + SKT_F + SV_F + SP_F + 128)
#define ATTN_SMEM_BYTES  (ATTN_SMEM_FLOATS * 4)

__global__ __launch_bounds__(256, 2) void attn_kernel(float* __restrict__ attn_out)
{
    extern __shared__ float sm[];
    float* sqT = sm;                          // [d][row] stride 132
    float* skT = sm + SQT_F;                  // [d][key] stride 68
    float* sv  = sm + SQT_F + SKT_F;          // [k][dim] stride 68
    float* sP  = sm + SQT_F + SKT_F + SV_F;   // [row][key] stride 68
    float* srow = sP + SP_F;                  // [128]

    const int tid = threadIdx.x;
    const int bh = blockIdx.y;
    const int q0 = blockIdx.x * 128;
    const float* Q = g_q + (size_t)bh * L_ * DH_;
    const float* K = g_k + (size_t)bh * L_ * DH_;
    const float* V = g_v + (size_t)bh * L_ * DH_;
    float* attn = attn_out + (size_t)bh * L_ * L_;

    {
        int lr = tid >> 1;
        int c0 = (tid & 1) * 32;
#pragma unroll
        for (int w = 0; w < 8; w++) {
            float4 qv = *(const float4*)(Q + (size_t)(q0 + lr) * DH_ + c0 + w * 4);
            sqT[(c0 + w * 4 + 0) * 132 + lr] = qv.x;
            sqT[(c0 + w * 4 + 1) * 132 + lr] = qv.y;
            sqT[(c0 + w * 4 + 2) * 132 + lr] = qv.z;
            sqT[(c0 + w * 4 + 3) * 132 + lr] = qv.w;
        }
    }

    const int ty = tid >> 4;   // rows ty*8 .. ty*8+7
    const int tx = tid & 15;   // keys/dims tx*4 .. tx*4+3

    unsigned long long oacc[8][2];
#pragma unroll
    for (int i = 0; i < 8; i++) { oacc[i][0] = 0ull; oacc[i][1] = 0ull; }
    float rsum[8];
#pragma unroll
    for (int i = 0; i < 8; i++) rsum[i] = 0.f;

    const int klr = tid >> 2;
    const int kc  = tid & 3;

    for (int kt = 0; kt < L_ / 64; kt++) {
        const int k0g = kt * 64;
#pragma unroll
        for (int jj = 0; jj < 4; jj++) {
            int d0 = kc * 4 + jj * 16;
            float4 kv = *(const float4*)(K + (size_t)(k0g + klr) * DH_ + d0);
            skT[(d0 + 0) * 68 + klr] = kv.x;
            skT[(d0 + 1) * 68 + klr] = kv.y;
            skT[(d0 + 2) * 68 + klr] = kv.z;
            skT[(d0 + 3) * 68 + klr] = kv.w;
            int vd = kc * 16 + jj * 4;
            float4 vv = *(const float4*)(V + (size_t)(k0g + klr) * DH_ + vd);
            *(float4*)&sv[klr * 68 + vd] = vv;
        }
        __syncthreads();

        unsigned long long s[4][4];
#pragma unroll
        for (int p = 0; p < 4; p++)
#pragma unroll
            for (int j = 0; j < 4; j++) s[p][j] = 0ull;

#pragma unroll 4
        for (int d = 0; d < 64; d++) {
            ulonglong2 qa = *(const ulonglong2*)&sqT[d * 132 + ty * 8];
            ulonglong2 qb = *(const ulonglong2*)&sqT[d * 132 + ty * 8 + 4];
            float4 kf = *(const float4*)&skT[d * 68 + tx * 4];
            float kj[4] = {kf.x, kf.y, kf.z, kf.w};
#pragma unroll
            for (int j = 0; j < 4; j++) {
                unsigned long long kk = pk2(kj[j], kj[j]);
                fma2(s[0][j], qa.x, kk);
                fma2(s[1][j], qa.y, kk);
                fma2(s[2][j], qb.x, kk);
                fma2(s[3][j], qb.y, kk);
            }
        }

        float ev[8][4];
#pragma unroll
        for (int p = 0; p < 4; p++)
#pragma unroll
            for (int j = 0; j < 4; j++) {
                float2 u = upk2(s[p][j]);
                ev[2 * p + 0][j] = __expf(u.x * 0.125f);
                ev[2 * p + 1][j] = __expf(u.y * 0.125f);
            }
#pragma unroll
        for (int i = 0; i < 8; i++) {
            float ls = ev[i][0] + ev[i][1] + ev[i][2] + ev[i][3];
#pragma unroll
            for (int off = 1; off < 16; off <<= 1)
                ls += __shfl_xor_sync(0xffffffffu, ls, off);
            rsum[i] += ls;
            float4 e4 = make_float4(ev[i][0], ev[i][1], ev[i][2], ev[i][3]);
            // fire-and-forget gmem store (output) + smem stage for AV
            *(float4*)(attn + (size_t)(q0 + ty * 8 + i) * L_ + k0g + tx * 4) = e4;
            *(float4*)&sP[(ty * 8 + i) * 68 + tx * 4] = e4;
        }

        __syncthreads();   // sP visible CTA-wide

        // AV: P from smem (broadcast LDS), V from smem
#pragma unroll 2
        for (int k = 0; k < 64; k += 4) {
            float4 pr[8];
#pragma unroll
            for (int i = 0; i < 8; i++)
                pr[i] = *(const float4*)&sP[(ty * 8 + i) * 68 + k];
#pragma unroll
            for (int t = 0; t < 4; t++) {
                ulonglong2 vt = *(const ulonglong2*)&sv[(k + t) * 68 + tx * 4];
#pragma unroll
                for (int i = 0; i < 8; i++) {
                    float pv = (t == 0) ? pr[i].x : (t == 1) ? pr[i].y
                             : (t == 2) ? pr[i].z : pr[i].w;
                    unsigned long long pp = pk2(pv, pv);
                    fma2(oacc[i][0], pp, vt.x);
                    fma2(oacc[i][1], pp, vt.y);
                }
            }
        }
        __syncthreads();   // AV done with sv/sP before next tile overwrites
    }

    if (tx == 0) {
#pragma unroll
        for (int i = 0; i < 8; i++) srow[ty * 8 + i] = rsum[i];
    }
    __syncthreads();

    const int bidx = bh >> 4;
    const int h = bh & 15;
#pragma unroll
    for (int i = 0; i < 8; i++) {
        float inv = 1.f / srow[ty * 8 + i];
        float2 u0 = upk2(oacc[i][0]);
        float2 u1 = upk2(oacc[i][1]);
        float4 o = make_float4(u0.x * inv, u0.y * inv, u1.x * inv, u1.y * inv);
        *(float4*)(g_hout + ((size_t)(bidx * L_) + q0 + ty * 8 + i) * DM_
                   + h * DH_ + tx * 4) = o;
    }

    // fused rescale of this CTA's 128 attn rows
#pragma unroll
    for (int i = 0; i < 8; i++) {
        float inv = 1.f / srow[ty * 8 + i];
        float* rowp = attn + (size_t)(q0 + ty * 8 + i) * L_;
#pragma unroll 4
        for (int j = 0; j < 32; j++) {
            float4* p = (float4*)(rowp + j * 64 + tx * 4);
            float4 v = *p;
            v.x *= inv; v.y *= inv; v.z *= inv; v.w *= inv;
            *p = v;
        }
    }
}

// ---------------------------------------------------------------------------
extern "C" void kernel_launch(void* const* d_in, const int* in_sizes, int n_in,
                              void* d_out, int out_size)
{
    (void)in_sizes; (void)n_in; (void)out_size;
    const float* x    = (const float*)d_in[0];
    const float* Wqkv = (const float*)d_in[1];
    const float* bqkv = (const float*)d_in[2];
    const float* Wout = (const float*)d_in[3];
    const float* bout = (const float*)d_in[4];
    float* out  = (float*)d_out;
    float* attn = out + OUT_ELEMS_;

    static int attr_done = 0;
    if (!attr_done) {
        cudaFuncSetAttribute(attn_kernel,
            cudaFuncAttributeMaxDynamicSharedMemorySize, ATTN_SMEM_BYTES);
        cudaFuncSetAttribute(gemm_mma_kernel<0>,
            cudaFuncAttributeMaxDynamicSharedMemorySize, GEMM_SMEM_BYTES);
        cudaFuncSetAttribute(gemm_mma_kernel<1>,
            cudaFuncAttributeMaxDynamicSharedMemorySize, GEMM_SMEM_BYTES);
        attr_done = 1;
    }

    float *xhi, *xlo, *wqhi, *wqlo, *wohi, *wolo, *hhi, *hlo, *hout;
    cudaGetSymbolAddress((void**)&xhi,  g_xhi);
    cudaGetSymbolAddress((void**)&xlo,  g_xlo);
    cudaGetSymbolAddress((void**)&wqhi, g_wqhi);
    cudaGetSymbolAddress((void**)&wqlo, g_wqlo);
    cudaGetSymbolAddress((void**)&wohi, g_wohi);
    cudaGetSymbolAddress((void**)&wolo, g_wolo);
    cudaGetSymbolAddress((void**)&hhi,  g_hhi);
    cudaGetSymbolAddress((void**)&hlo,  g_hlo);
    cudaGetSymbolAddress((void**)&hout, g_hout);

    // operand decompositions
    decomp_kernel<<<OUT_ELEMS_ / 4 / 256, 256>>>(x, xhi, xlo);
    decomp_t_kernel<<<dim3(N3_ / 32, DM_ / 32), 256>>>(Wqkv, wqhi, wqlo, DM_, N3_);
    decomp_t_kernel<<<dim3(DM_ / 32, DM_ / 32), 256>>>(Wout, wohi, wolo, DM_, DM_);

    // QKV projection (mma.sync tf32 3x)
    gemm_mma_kernel<1><<<dim3(N3_ / 128, (B_ * L_) / 128), 256, GEMM_SMEM_BYTES>>>(
        xhi, xlo, wqhi, wqlo, bqkv, nullptr);

    // attention + fused rescale
    attn_kernel<<<dim3(L_ / 128, BH_), 256, ATTN_SMEM_BYTES>>>(attn);

    // out projection
    decomp_kernel<<<OUT_ELEMS_ / 4 / 256, 256>>>(hout, hhi, hlo);
    gemm_mma_kernel<0><<<dim3(DM_ / 128, (B_ * L_) / 128), 256, GEMM_SMEM_BYTES>>>(
        hhi, hlo, wohi, wolo, bout, out);
}

// round 10
// speedup vs baseline: 1.3307x; 1.1141x over previous
#include <cuda_runtime.h>
#include <cstdint>

#define B_ 4
#define L_ 2048
#define H_ 16
#define DH_ 64
#define DM_ 1024
#define N3_ 3072
#define BH_ (B_*H_)
#define OUT_ELEMS_ (B_*L_*DM_)   // 8388608

// Scratch (device globals: allocation-free per harness rules)
__device__ float g_q[BH_*L_*DH_];
__device__ float g_k[BH_*L_*DH_];
__device__ float g_v[BH_*L_*DH_];
__device__ float g_hout[B_*L_*DM_];

// tf32 hi/lo decompositions
__device__ float g_xhi[B_*L_*DM_];
__device__ float g_xlo[B_*L_*DM_];
__device__ float g_wqhi[N3_*DM_];    // [n][k] (transposed W_qkv)
__device__ float g_wqlo[N3_*DM_];
__device__ float g_wohi[DM_*DM_];    // [n][k] (transposed W_out)
__device__ float g_wolo[DM_*DM_];
__device__ float g_hhi[B_*L_*DM_];
__device__ float g_hlo[B_*L_*DM_];

// ---------------------------------------------------------------------------
// Helpers
// ---------------------------------------------------------------------------
__device__ __forceinline__ uint32_t smem_u32(const void* p) {
    uint32_t a;
    asm("{ .reg .u64 t; cvta.to.shared.u64 t, %1; cvt.u32.u64 %0, t; }"
        : "=r"(a) : "l"(p));
    return a;
}
__device__ __forceinline__ void cpa16(uint32_t dst, const float* src) {
    asm volatile("cp.async.cg.shared.global [%0], [%1], 16;" :: "r"(dst), "l"(src));
}
__device__ __forceinline__ float2 tf32split(float a) {
    uint32_t hb;
    asm("cvt.rna.tf32.f32 %0, %1;" : "=r"(hb) : "f"(a));
    float hi = __uint_as_float(hb);
    float lo = a - hi;
    uint32_t lb;
    asm("cvt.rna.tf32.f32 %0, %1;" : "=r"(lb) : "f"(lo));
    return make_float2(hi, __uint_as_float(lb));
}
__device__ __forceinline__ float tf32rna(float a) {
    uint32_t b;
    asm("cvt.rna.tf32.f32 %0, %1;" : "=r"(b) : "f"(a));
    return __uint_as_float(b);
}
// m16n8k8 tf32 MMA (baseline PTX, works on compute_103)
__device__ __forceinline__ void mma8(float c[4], const float a[4], const float b[2]) {
    asm volatile(
        "mma.sync.aligned.m16n8k8.row.col.f32.tf32.tf32.f32 "
        "{%0,%1,%2,%3}, {%4,%5,%6,%7}, {%8,%9}, {%0,%1,%2,%3};"
        : "+f"(c[0]), "+f"(c[1]), "+f"(c[2]), "+f"(c[3])
        : "r"(__float_as_uint(a[0])), "r"(__float_as_uint(a[1])),
          "r"(__float_as_uint(a[2])), "r"(__float_as_uint(a[3])),
          "r"(__float_as_uint(b[0])), "r"(__float_as_uint(b[1])));
}

// f32x2 packed FMA (attn score loop)
__device__ __forceinline__ unsigned long long pk2(float x, float y) {
    unsigned long long r;
    asm("mov.b64 %0, {%1, %2};" : "=l"(r) : "f"(x), "f"(y));
    return r;
}
__device__ __forceinline__ float2 upk2(unsigned long long v) {
    float lo, hi;
    asm("mov.b64 {%0, %1}, %2;" : "=f"(lo), "=f"(hi) : "l"(v));
    return make_float2(lo, hi);
}
__device__ __forceinline__ void fma2(unsigned long long& d,
                                     unsigned long long a,
                                     unsigned long long b) {
    asm("fma.rn.f32x2 %0, %1, %2, %3;" : "=l"(d) : "l"(a), "l"(b), "l"(d));
}

// ---------------------------------------------------------------------------
// Decomposition kernels
// ---------------------------------------------------------------------------
__global__ __launch_bounds__(256) void decomp_kernel(
    const float* __restrict__ src, float* __restrict__ hi, float* __restrict__ lo)
{
    int i = blockIdx.x * 256 + threadIdx.x;
    float4 v = ((const float4*)src)[i];
    float2 sx = tf32split(v.x), sy = tf32split(v.y);
    float2 sz = tf32split(v.z), sw = tf32split(v.w);
    ((float4*)hi)[i] = make_float4(sx.x, sy.x, sz.x, sw.x);
    ((float4*)lo)[i] = make_float4(sx.y, sy.y, sz.y, sw.y);
}

// W[k][n] -> hi/lo [n][k]
__global__ __launch_bounds__(256) void decomp_t_kernel(
    const float* __restrict__ src, float* __restrict__ dhi, float* __restrict__ dlo,
    int K, int N)
{
    __shared__ float t[32][33];
    int k0 = blockIdx.y * 32, n0 = blockIdx.x * 32;
    int r = threadIdx.x >> 3;
    int c4 = (threadIdx.x & 7) * 4;
    float4 v = *(const float4*)(src + (size_t)(k0 + r) * N + n0 + c4);
    t[r][c4 + 0] = v.x; t[r][c4 + 1] = v.y; t[r][c4 + 2] = v.z; t[r][c4 + 3] = v.w;
    __syncthreads();
    float2 s0 = tf32split(t[c4 + 0][r]);
    float2 s1 = tf32split(t[c4 + 1][r]);
    float2 s2 = tf32split(t[c4 + 2][r]);
    float2 s3 = tf32split(t[c4 + 3][r]);
    *(float4*)(dhi + (size_t)(n0 + r) * K + k0 + c4) =
        make_float4(s0.x, s1.x, s2.x, s3.x);
    *(float4*)(dlo + (size_t)(n0 + r) * K + k0 + c4) =
        make_float4(s0.y, s1.y, s2.y, s3.y);
}

// ---------------------------------------------------------------------------
// mma.sync tf32 3x GEMM (R7-proven, unchanged).
// MODE 0: out projection  (C -> Cout[m][n] + bias)
// MODE 1: qkv projection  (C + bias scattered into g_q/g_k/g_v)
// ---------------------------------------------------------------------------
#define ARR_F 4608              // 128*36 floats
#define STAGE_F (4 * ARR_F)     // 18432 floats
#define GEMM_SMEM_BYTES (3 * STAGE_F * 4)   // 221184

template <int MODE>
__global__ __launch_bounds__(256, 1) void gemm_mma_kernel(
    const float* __restrict__ Ahi, const float* __restrict__ Alo,
    const float* __restrict__ Bhi, const float* __restrict__ Blo,
    const float* __restrict__ bias, float* __restrict__ Cout)
{
    extern __shared__ float gsm[];
    const uint32_t sbase = smem_u32(gsm);
    const int tid = threadIdx.x;
    const int wid = tid >> 5;
    const int lane = tid & 31;
    const int grp = lane >> 2;      // 0..7
    const int tg = lane & 3;        // 0..3
    const int n0 = blockIdx.x * 128;
    const int m0 = blockIdx.y * 128;

    const int lrow = tid >> 1;
    const int lg4 = (tid & 1) * 4;

    const float* srcA_hi = Ahi + (size_t)(m0 + lrow) * DM_ + lg4 * 4;
    const float* srcA_lo = Alo + (size_t)(m0 + lrow) * DM_ + lg4 * 4;
    const float* srcB_hi = Bhi + (size_t)(n0 + lrow) * DM_ + lg4 * 4;
    const float* srcB_lo = Blo + (size_t)(n0 + lrow) * DM_ + lg4 * 4;

    auto load_chunk = [&](int c) {
        if (c < 32) {
            const int st = c % 3;
            const uint32_t sb = sbase + (st * STAGE_F) * 4;
            const uint32_t dbase = sb + (lrow * 36 + lg4 * 4) * 4;
            const int k0 = c * 32;
#pragma unroll
            for (int j = 0; j < 4; j++) {
                cpa16(dbase + 0 * ARR_F * 4 + j * 16, srcA_hi + k0 + j * 4);
                cpa16(dbase + 1 * ARR_F * 4 + j * 16, srcA_lo + k0 + j * 4);
                cpa16(dbase + 2 * ARR_F * 4 + j * 16, srcB_hi + k0 + j * 4);
                cpa16(dbase + 3 * ARR_F * 4 + j * 16, srcB_lo + k0 + j * 4);
            }
        }
        asm volatile("cp.async.commit_group;" ::: "memory");
    };

    const int wm = wid & 1;
    const int wn = wid >> 1;

    float acc[4][4][4];
#pragma unroll
    for (int mf = 0; mf < 4; mf++)
#pragma unroll
        for (int nf = 0; nf < 4; nf++)
#pragma unroll
            for (int e = 0; e < 4; e++) acc[mf][nf][e] = 0.f;

    load_chunk(0);
    load_chunk(1);

    for (int c = 0; c < 32; c++) {
        asm volatile("cp.async.wait_group 1;" ::: "memory");
        __syncthreads();

        const float* sb = gsm + (c % 3) * STAGE_F;
        const float* sAhi = sb;
        const float* sAlo = sb + ARR_F;
        const float* sBhi = sb + 2 * ARR_F;
        const float* sBlo = sb + 3 * ARR_F;

#pragma unroll
        for (int k8 = 0; k8 < 4; k8++) {
            const int kk = k8 * 8;
            float aH[4][4], aL[4][4];
#pragma unroll
            for (int mf = 0; mf < 4; mf++) {
                int mr = wm * 64 + mf * 16 + grp;
                aH[mf][0] = sAhi[(mr) * 36 + kk + tg];
                aH[mf][1] = sAhi[(mr + 8) * 36 + kk + tg];
                aH[mf][2] = sAhi[(mr) * 36 + kk + tg + 4];
                aH[mf][3] = sAhi[(mr + 8) * 36 + kk + tg + 4];
                aL[mf][0] = sAlo[(mr) * 36 + kk + tg];
                aL[mf][1] = sAlo[(mr + 8) * 36 + kk + tg];
                aL[mf][2] = sAlo[(mr) * 36 + kk + tg + 4];
                aL[mf][3] = sAlo[(mr + 8) * 36 + kk + tg + 4];
            }
            float bH[4][2], bL[4][2];
#pragma unroll
            for (int nf = 0; nf < 4; nf++) {
                int nr = wn * 32 + nf * 8 + grp;
                bH[nf][0] = sBhi[nr * 36 + kk + tg];
                bH[nf][1] = sBhi[nr * 36 + kk + tg + 4];
                bL[nf][0] = sBlo[nr * 36 + kk + tg];
                bL[nf][1] = sBlo[nr * 36 + kk + tg + 4];
            }
#pragma unroll
            for (int mf = 0; mf < 4; mf++)
#pragma unroll
                for (int nf = 0; nf < 4; nf++) {
                    mma8(acc[mf][nf], aH[mf], bH[nf]);
                    mma8(acc[mf][nf], aH[mf], bL[nf]);
                    mma8(acc[mf][nf], aL[mf], bH[nf]);
                }
        }
        __syncthreads();
        load_chunk(c + 2);
    }

#pragma unroll
    for (int mf = 0; mf < 4; mf++) {
#pragma unroll
        for (int nf = 0; nf < 4; nf++) {
            int m = m0 + wm * 64 + mf * 16 + grp;
            int n = n0 + wn * 32 + nf * 8 + tg * 2;
            float b0 = __ldg(bias + n), b1 = __ldg(bias + n + 1);
            float2 v0 = make_float2(acc[mf][nf][0] + b0, acc[mf][nf][1] + b1);
            float2 v1 = make_float2(acc[mf][nf][2] + b0, acc[mf][nf][3] + b1);
            if (MODE == 0) {
                *(float2*)(Cout + (size_t)m * DM_ + n) = v0;
                *(float2*)(Cout + (size_t)(m + 8) * DM_ + n) = v1;
            } else {
                int mat = n >> 10;
                int cc = n & 1023;
                int h = cc >> 6, dd = cc & 63;
                float* dst = (mat == 0) ? g_q : (mat == 1) ? g_k : g_v;
                int bidx = m >> 11;
                int l = m & 2047;
                *(float2*)(dst + (((size_t)(bidx * H_ + h)) * L_ + l) * DH_ + dd) = v0;
                *(float2*)(dst + (((size_t)(bidx * H_ + h)) * L_ + l + 8) * DH_ + dd) = v1;
            }
        }
    }
}

// ---------------------------------------------------------------------------
// Fused attention: 128 q-rows/CTA, 64-key tiles.
//  - scores: FFMA2 (R9-proven), e -> gmem (fp32) + sP (tf32-rounded)
//  - AV: mma.sync m16n8k8 tf32 on P (sP) x V (sv) -- moves 50% of attn MACs
//    off the fma pipe with ZERO extra smem; occ 2 preserved.
//  - fused rescale of this CTA's attn rows at the end (R9-proven).
// smem floats: sqT[64][132]=8448, skT[64][68]=4352, sv[64][68]=4352,
//              sP[128][68]=8704, srow[128]  -> 25984 floats = 103936 B
// ---------------------------------------------------------------------------
#define SQT_F 8448
#define SKT_F 4352
#define SV_F  4352
#define SP_F  8704
#define ATTN_SMEM_FLOATS (SQT_F + SKT_F + SV_F + SP_F + 128)
#define ATTN_SMEM_BYTES  (ATTN_SMEM_FLOATS * 4)

__global__ __launch_bounds__(256, 2) void attn_kernel(float* __restrict__ attn_out)
{
    extern __shared__ float sm[];
    float* sqT = sm;                          // [d][row] stride 132
    float* skT = sm + SQT_F;                  // [d][key] stride 68
    float* sv  = sm + SQT_F + SKT_F;          // [k][dim] stride 68
    float* sP  = sm + SQT_F + SKT_F + SV_F;   // [row][key] stride 68 (tf32)
    float* srow = sP + SP_F;                  // [128]

    const int tid = threadIdx.x;
    const int bh = blockIdx.y;
    const int q0 = blockIdx.x * 128;
    const float* Q = g_q + (size_t)bh * L_ * DH_;
    const float* K = g_k + (size_t)bh * L_ * DH_;
    const float* V = g_v + (size_t)bh * L_ * DH_;
    float* attn = attn_out + (size_t)bh * L_ * L_;

    {
        int lr = tid >> 1;
        int c0 = (tid & 1) * 32;
#pragma unroll
        for (int w = 0; w < 8; w++) {
            float4 qv = *(const float4*)(Q + (size_t)(q0 + lr) * DH_ + c0 + w * 4);
            sqT[(c0 + w * 4 + 0) * 132 + lr] = qv.x;
            sqT[(c0 + w * 4 + 1) * 132 + lr] = qv.y;
            sqT[(c0 + w * 4 + 2) * 132 + lr] = qv.z;
            sqT[(c0 + w * 4 + 3) * 132 + lr] = qv.w;
        }
    }

    // score-phase mapping (R9-proven)
    const int ty = tid >> 4;   // rows ty*8 .. ty*8+7
    const int tx = tid & 15;   // keys tx*4 .. tx*4+3
    // AV-MMA mapping
    const int wid = tid >> 5;
    const int lane = tid & 31;
    const int grp = lane >> 2;
    const int tg = lane & 3;
    const int mq = wid & 3;    // q-group of 32 rows
    const int dh = wid >> 2;   // d-half of 32 dims

    float facc[2][4][4];
#pragma unroll
    for (int mf = 0; mf < 2; mf++)
#pragma unroll
        for (int nf = 0; nf < 4; nf++)
#pragma unroll
            for (int e = 0; e < 4; e++) facc[mf][nf][e] = 0.f;

    float rsum[8];
#pragma unroll
    for (int i = 0; i < 8; i++) rsum[i] = 0.f;

    const int klr = tid >> 2;
    const int kc  = tid & 3;

    for (int kt = 0; kt < L_ / 64; kt++) {
        const int k0g = kt * 64;
#pragma unroll
        for (int jj = 0; jj < 4; jj++) {
            int d0 = kc * 4 + jj * 16;
            float4 kv = *(const float4*)(K + (size_t)(k0g + klr) * DH_ + d0);
            skT[(d0 + 0) * 68 + klr] = kv.x;
            skT[(d0 + 1) * 68 + klr] = kv.y;
            skT[(d0 + 2) * 68 + klr] = kv.z;
            skT[(d0 + 3) * 68 + klr] = kv.w;
            int vd = kc * 16 + jj * 4;
            float4 vv = *(const float4*)(V + (size_t)(k0g + klr) * DH_ + vd);
            *(float4*)&sv[klr * 68 + vd] = vv;
        }
        __syncthreads();

        // ---- scores (FFMA2, R9-proven) ----
        unsigned long long s[4][4];
#pragma unroll
        for (int p = 0; p < 4; p++)
#pragma unroll
            for (int j = 0; j < 4; j++) s[p][j] = 0ull;

#pragma unroll 4
        for (int d = 0; d < 64; d++) {
            ulonglong2 qa = *(const ulonglong2*)&sqT[d * 132 + ty * 8];
            ulonglong2 qb = *(const ulonglong2*)&sqT[d * 132 + ty * 8 + 4];
            float4 kf = *(const float4*)&skT[d * 68 + tx * 4];
            float kj[4] = {kf.x, kf.y, kf.z, kf.w};
#pragma unroll
            for (int j = 0; j < 4; j++) {
                unsigned long long kk = pk2(kj[j], kj[j]);
                fma2(s[0][j], qa.x, kk);
                fma2(s[1][j], qa.y, kk);
                fma2(s[2][j], qb.x, kk);
                fma2(s[3][j], qb.y, kk);
            }
        }

        float ev[8][4];
#pragma unroll
        for (int p = 0; p < 4; p++)
#pragma unroll
            for (int j = 0; j < 4; j++) {
                float2 u = upk2(s[p][j]);
                ev[2 * p + 0][j] = __expf(u.x * 0.125f);
                ev[2 * p + 1][j] = __expf(u.y * 0.125f);
            }
#pragma unroll
        for (int i = 0; i < 8; i++) {
            float ls = ev[i][0] + ev[i][1] + ev[i][2] + ev[i][3];
#pragma unroll
            for (int off = 1; off < 16; off <<= 1)
                ls += __shfl_xor_sync(0xffffffffu, ls, off);
            rsum[i] += ls;
            float4 e4 = make_float4(ev[i][0], ev[i][1], ev[i][2], ev[i][3]);
            // full-precision e -> gmem (attn output)
            *(float4*)(attn + (size_t)(q0 + ty * 8 + i) * L_ + k0g + tx * 4) = e4;
            // tf32-rounded e -> sP for the AV MMA
            float4 e4r = make_float4(tf32rna(e4.x), tf32rna(e4.y),
                                     tf32rna(e4.z), tf32rna(e4.w));
            *(float4*)&sP[(ty * 8 + i) * 68 + tx * 4] = e4r;
        }

        __syncthreads();   // sP visible CTA-wide

        // ---- AV on the tensor pipe: O += P(sP) x V(sv) ----
#pragma unroll
        for (int k8 = 0; k8 < 8; k8++) {
            const int kk = k8 * 8;
            float a0[4], a1[4];
            const int mr = mq * 32 + grp;
            a0[0] = sP[(mr) * 68 + kk + tg];
            a0[1] = sP[(mr + 8) * 68 + kk + tg];
            a0[2] = sP[(mr) * 68 + kk + tg + 4];
            a0[3] = sP[(mr + 8) * 68 + kk + tg + 4];
            a1[0] = sP[(mr + 16) * 68 + kk + tg];
            a1[1] = sP[(mr + 24) * 68 + kk + tg];
            a1[2] = sP[(mr + 16) * 68 + kk + tg + 4];
            a1[3] = sP[(mr + 24) * 68 + kk + tg + 4];
            float b[4][2];
#pragma unroll
            for (int nf = 0; nf < 4; nf++) {
                int nd = dh * 32 + nf * 8 + grp;
                b[nf][0] = sv[(kk + tg) * 68 + nd];
                b[nf][1] = sv[(kk + tg + 4) * 68 + nd];
            }
#pragma unroll
            for (int nf = 0; nf < 4; nf++) {
                mma8(facc[0][nf], a0, b[nf]);
                mma8(facc[1][nf], a1, b[nf]);
            }
        }
        __syncthreads();   // done with sP/sv/skT before next tile overwrites
    }

    if (tx == 0) {
#pragma unroll
        for (int i = 0; i < 8; i++) srow[ty * 8 + i] = rsum[i];
    }
    __syncthreads();

    const int bidx = bh >> 4;
    const int h = bh & 15;

    // AV epilogue: normalize fragments, write hout
#pragma unroll
    for (int mf = 0; mf < 2; mf++) {
#pragma unroll
        for (int nf = 0; nf < 4; nf++) {
            int r0 = mq * 32 + mf * 16 + grp;
            int nd = dh * 32 + nf * 8 + tg * 2;
            float i0 = 1.f / srow[r0];
            float i1 = 1.f / srow[r0 + 8];
            float* p0 = g_hout + ((size_t)(bidx * L_) + q0 + r0) * DM_
                        + h * DH_ + nd;
            *(float2*)p0 = make_float2(facc[mf][nf][0] * i0,
                                       facc[mf][nf][1] * i0);
            *(float2*)(p0 + (size_t)8 * DM_) =
                make_float2(facc[mf][nf][2] * i1, facc[mf][nf][3] * i1);
        }
    }

    // fused rescale of this CTA's 128 attn rows
#pragma unroll
    for (int i = 0; i < 8; i++) {
        float inv = 1.f / srow[ty * 8 + i];
        float* rowp = attn + (size_t)(q0 + ty * 8 + i) * L_;
#pragma unroll 4
        for (int j = 0; j < 32; j++) {
            float4* p = (float4*)(rowp + j * 64 + tx * 4);
            float4 v = *p;
            v.x *= inv; v.y *= inv; v.z *= inv; v.w *= inv;
            *p = v;
        }
    }
}

// ---------------------------------------------------------------------------
extern "C" void kernel_launch(void* const* d_in, const int* in_sizes, int n_in,
                              void* d_out, int out_size)
{
    (void)in_sizes; (void)n_in; (void)out_size;
    const float* x    = (const float*)d_in[0];
    const float* Wqkv = (const float*)d_in[1];
    const float* bqkv = (const float*)d_in[2];
    const float* Wout = (const float*)d_in[3];
    const float* bout = (const float*)d_in[4];
    float* out  = (float*)d_out;
    float* attn = out + OUT_ELEMS_;

    static int attr_done = 0;
    if (!attr_done) {
        cudaFuncSetAttribute(attn_kernel,
            cudaFuncAttributeMaxDynamicSharedMemorySize, ATTN_SMEM_BYTES);
        cudaFuncSetAttribute(gemm_mma_kernel<0>,
            cudaFuncAttributeMaxDynamicSharedMemorySize, GEMM_SMEM_BYTES);
        cudaFuncSetAttribute(gemm_mma_kernel<1>,
            cudaFuncAttributeMaxDynamicSharedMemorySize, GEMM_SMEM_BYTES);
        attr_done = 1;
    }

    float *xhi, *xlo, *wqhi, *wqlo, *wohi, *wolo, *hhi, *hlo, *hout;
    cudaGetSymbolAddress((void**)&xhi,  g_xhi);
    cudaGetSymbolAddress((void**)&xlo,  g_xlo);
    cudaGetSymbolAddress((void**)&wqhi, g_wqhi);
    cudaGetSymbolAddress((void**)&wqlo, g_wqlo);
    cudaGetSymbolAddress((void**)&wohi, g_wohi);
    cudaGetSymbolAddress((void**)&wolo, g_wolo);
    cudaGetSymbolAddress((void**)&hhi,  g_hhi);
    cudaGetSymbolAddress((void**)&hlo,  g_hlo);
    cudaGetSymbolAddress((void**)&hout, g_hout);

    // operand decompositions
    decomp_kernel<<<OUT_ELEMS_ / 4 / 256, 256>>>(x, xhi, xlo);
    decomp_t_kernel<<<dim3(N3_ / 32, DM_ / 32), 256>>>(Wqkv, wqhi, wqlo, DM_, N3_);
    decomp_t_kernel<<<dim3(DM_ / 32, DM_ / 32), 256>>>(Wout, wohi, wolo, DM_, DM_);

    // QKV projection (mma.sync tf32 3x)
    gemm_mma_kernel<1><<<dim3(N3_ / 128, (B_ * L_) / 128), 256, GEMM_SMEM_BYTES>>>(
        xhi, xlo, wqhi, wqlo, bqkv, nullptr);

    // attention (AV on tensor pipe) + fused rescale
    attn_kernel<<<dim3(L_ / 128, BH_), 256, ATTN_SMEM_BYTES>>>(attn);

    // out projection
    decomp_kernel<<<OUT_ELEMS_ / 4 / 256, 256>>>(hout, hhi, hlo);
    gemm_mma_kernel<0><<<dim3(DM_ / 128, (B_ * L_) / 128), 256, GEMM_SMEM_BYTES>>>(
        hhi, hlo, wohi, wolo, bout, out);
}

// round 11
// speedup vs baseline: 1.4617x; 1.0985x over previous
#include <cuda_runtime.h>
#include <cstdint>

#define B_ 4
#define L_ 2048
#define H_ 16
#define DH_ 64
#define DM_ 1024
#define N3_ 3072
#define BH_ (B_*H_)
#define OUT_ELEMS_ (B_*L_*DM_)   // 8388608

// Scratch (device globals: allocation-free per harness rules)
__device__ float g_q[BH_*L_*DH_];
__device__ float g_k[BH_*L_*DH_];
__device__ float g_v[BH_*L_*DH_];

// tf32 hi/lo decompositions
__device__ float g_xhi[B_*L_*DM_];
__device__ float g_xlo[B_*L_*DM_];
__device__ float g_wqhi[N3_*DM_];    // [n][k] (transposed W_qkv)
__device__ float g_wqlo[N3_*DM_];
__device__ float g_wohi[DM_*DM_];    // [n][k] (transposed W_out)
__device__ float g_wolo[DM_*DM_];
__device__ float g_hhi[B_*L_*DM_];   // attn writes hout pre-split
__device__ float g_hlo[B_*L_*DM_];

// ---------------------------------------------------------------------------
// Helpers
// ---------------------------------------------------------------------------
__device__ __forceinline__ uint32_t smem_u32(const void* p) {
    uint32_t a;
    asm("{ .reg .u64 t; cvta.to.shared.u64 t, %1; cvt.u32.u64 %0, t; }"
        : "=r"(a) : "l"(p));
    return a;
}
__device__ __forceinline__ void cpa16(uint32_t dst, const float* src) {
    asm volatile("cp.async.cg.shared.global [%0], [%1], 16;" :: "r"(dst), "l"(src));
}
__device__ __forceinline__ float2 tf32split(float a) {
    uint32_t hb;
    asm("cvt.rna.tf32.f32 %0, %1;" : "=r"(hb) : "f"(a));
    float hi = __uint_as_float(hb);
    float lo = a - hi;
    uint32_t lb;
    asm("cvt.rna.tf32.f32 %0, %1;" : "=r"(lb) : "f"(lo));
    return make_float2(hi, __uint_as_float(lb));
}
__device__ __forceinline__ float tf32rna(float a) {
    uint32_t b;
    asm("cvt.rna.tf32.f32 %0, %1;" : "=r"(b) : "f"(a));
    return __uint_as_float(b);
}
// m16n8k8 tf32 MMA (baseline PTX, works on compute_103)
__device__ __forceinline__ void mma8(float c[4], const float a[4], const float b[2]) {
    asm volatile(
        "mma.sync.aligned.m16n8k8.row.col.f32.tf32.tf32.f32 "
        "{%0,%1,%2,%3}, {%4,%5,%6,%7}, {%8,%9}, {%0,%1,%2,%3};"
        : "+f"(c[0]), "+f"(c[1]), "+f"(c[2]), "+f"(c[3])
        : "r"(__float_as_uint(a[0])), "r"(__float_as_uint(a[1])),
          "r"(__float_as_uint(a[2])), "r"(__float_as_uint(a[3])),
          "r"(__float_as_uint(b[0])), "r"(__float_as_uint(b[1])));
}

// f32x2 packed FMA (attn score loop)
__device__ __forceinline__ unsigned long long pk2(float x, float y) {
    unsigned long long r;
    asm("mov.b64 %0, {%1, %2};" : "=l"(r) : "f"(x), "f"(y));
    return r;
}
__device__ __forceinline__ float2 upk2(unsigned long long v) {
    float lo, hi;
    asm("mov.b64 {%0, %1}, %2;" : "=f"(lo), "=f"(hi) : "l"(v));
    return make_float2(lo, hi);
}
__device__ __forceinline__ void fma2(unsigned long long& d,
                                     unsigned long long a,
                                     unsigned long long b) {
    asm("fma.rn.f32x2 %0, %1, %2, %3;" : "=l"(d) : "l"(a), "l"(b), "l"(d));
}

// ---------------------------------------------------------------------------
// Decomposition kernels
// ---------------------------------------------------------------------------
__global__ __launch_bounds__(256) void decomp_kernel(
    const float* __restrict__ src, float* __restrict__ hi, float* __restrict__ lo)
{
    int i = blockIdx.x * 256 + threadIdx.x;
    float4 v = ((const float4*)src)[i];
    float2 sx = tf32split(v.x), sy = tf32split(v.y);
    float2 sz = tf32split(v.z), sw = tf32split(v.w);
    ((float4*)hi)[i] = make_float4(sx.x, sy.x, sz.x, sw.x);
    ((float4*)lo)[i] = make_float4(sx.y, sy.y, sz.y, sw.y);
}

// W[k][n] -> hi/lo [n][k]
__global__ __launch_bounds__(256) void decomp_t_kernel(
    const float* __restrict__ src, float* __restrict__ dhi, float* __restrict__ dlo,
    int K, int N)
{
    __shared__ float t[32][33];
    int k0 = blockIdx.y * 32, n0 = blockIdx.x * 32;
    int r = threadIdx.x >> 3;
    int c4 = (threadIdx.x & 7) * 4;
    float4 v = *(const float4*)(src + (size_t)(k0 + r) * N + n0 + c4);
    t[r][c4 + 0] = v.x; t[r][c4 + 1] = v.y; t[r][c4 + 2] = v.z; t[r][c4 + 3] = v.w;
    __syncthreads();
    float2 s0 = tf32split(t[c4 + 0][r]);
    float2 s1 = tf32split(t[c4 + 1][r]);
    float2 s2 = tf32split(t[c4 + 2][r]);
    float2 s3 = tf32split(t[c4 + 3][r]);
    *(float4*)(dhi + (size_t)(n0 + r) * K + k0 + c4) =
        make_float4(s0.x, s1.x, s2.x, s3.x);
    *(float4*)(dlo + (size_t)(n0 + r) * K + k0 + c4) =
        make_float4(s0.y, s1.y, s2.y, s3.y);
}

// ---------------------------------------------------------------------------
// mma.sync tf32 3x GEMM.  NOW: k-chunk 16, 2 stages, 80 KB smem -> 2 CTA/SM.
// MODE 0: out projection  (C -> Cout[m][n] + bias)
// MODE 1: qkv projection  (C + bias scattered into g_q/g_k/g_v)
// ---------------------------------------------------------------------------
#define CH_F 20                  // smem row stride (16 + 4 pad)
#define ARR_F (128 * CH_F)       // 2560 floats per operand array
#define STAGE_F (4 * ARR_F)      // 10240 floats per stage
#define GEMM_SMEM_BYTES (2 * STAGE_F * 4)   // 81920
#define NCHUNK 64                // 1024 / 16

template <int MODE>
__global__ __launch_bounds__(256, 2) void gemm_mma_kernel(
    const float* __restrict__ Ahi, const float* __restrict__ Alo,
    const float* __restrict__ Bhi, const float* __restrict__ Blo,
    const float* __restrict__ bias, float* __restrict__ Cout)
{
    extern __shared__ float gsm[];
    const uint32_t sbase = smem_u32(gsm);
    const int tid = threadIdx.x;
    const int wid = tid >> 5;
    const int lane = tid & 31;
    const int grp = lane >> 2;      // 0..7
    const int tg = lane & 3;        // 0..3
    const int n0 = blockIdx.x * 128;
    const int m0 = blockIdx.y * 128;

    const int lrow = tid >> 1;          // 0..127
    const int lg = (tid & 1) * 8;       // floats lg..lg+7

    const float* srcA_hi = Ahi + (size_t)(m0 + lrow) * DM_ + lg;
    const float* srcA_lo = Alo + (size_t)(m0 + lrow) * DM_ + lg;
    const float* srcB_hi = Bhi + (size_t)(n0 + lrow) * DM_ + lg;
    const float* srcB_lo = Blo + (size_t)(n0 + lrow) * DM_ + lg;

    auto load_chunk = [&](int c) {
        if (c < NCHUNK) {
            const uint32_t sb = sbase + ((c & 1) * STAGE_F) * 4;
            const uint32_t dbase = sb + (lrow * CH_F + lg) * 4;
            const int k0 = c * 16;
            cpa16(dbase + 0 * ARR_F * 4,      srcA_hi + k0);
            cpa16(dbase + 0 * ARR_F * 4 + 16, srcA_hi + k0 + 4);
            cpa16(dbase + 1 * ARR_F * 4,      srcA_lo + k0);
            cpa16(dbase + 1 * ARR_F * 4 + 16, srcA_lo + k0 + 4);
            cpa16(dbase + 2 * ARR_F * 4,      srcB_hi + k0);
            cpa16(dbase + 2 * ARR_F * 4 + 16, srcB_hi + k0 + 4);
            cpa16(dbase + 3 * ARR_F * 4,      srcB_lo + k0);
            cpa16(dbase + 3 * ARR_F * 4 + 16, srcB_lo + k0 + 4);
        }
        asm volatile("cp.async.commit_group;" ::: "memory");
    };

    const int wm = wid & 1;
    const int wn = wid >> 1;

    float acc[4][4][4];
#pragma unroll
    for (int mf = 0; mf < 4; mf++)
#pragma unroll
        for (int nf = 0; nf < 4; nf++)
#pragma unroll
            for (int e = 0; e < 4; e++) acc[mf][nf][e] = 0.f;

    load_chunk(0);
    load_chunk(1);

    for (int c = 0; c < NCHUNK; c++) {
        asm volatile("cp.async.wait_group 1;" ::: "memory");
        __syncthreads();

        const float* sb = gsm + (c & 1) * STAGE_F;
        const float* sAhi = sb;
        const float* sAlo = sb + ARR_F;
        const float* sBhi = sb + 2 * ARR_F;
        const float* sBlo = sb + 3 * ARR_F;

#pragma unroll
        for (int k8 = 0; k8 < 2; k8++) {
            const int kk = k8 * 8;
            float aH[4][4], aL[4][4];
#pragma unroll
            for (int mf = 0; mf < 4; mf++) {
                int mr = wm * 64 + mf * 16 + grp;
                aH[mf][0] = sAhi[(mr) * CH_F + kk + tg];
                aH[mf][1] = sAhi[(mr + 8) * CH_F + kk + tg];
                aH[mf][2] = sAhi[(mr) * CH_F + kk + tg + 4];
                aH[mf][3] = sAhi[(mr + 8) * CH_F + kk + tg + 4];
                aL[mf][0] = sAlo[(mr) * CH_F + kk + tg];
                aL[mf][1] = sAlo[(mr + 8) * CH_F + kk + tg];
                aL[mf][2] = sAlo[(mr) * CH_F + kk + tg + 4];
                aL[mf][3] = sAlo[(mr + 8) * CH_F + kk + tg + 4];
            }
            float bH[4][2], bL[4][2];
#pragma unroll
            for (int nf = 0; nf < 4; nf++) {
                int nr = wn * 32 + nf * 8 + grp;
                bH[nf][0] = sBhi[nr * CH_F + kk + tg];
                bH[nf][1] = sBhi[nr * CH_F + kk + tg + 4];
                bL[nf][0] = sBlo[nr * CH_F + kk + tg];
                bL[nf][1] = sBlo[nr * CH_F + kk + tg + 4];
            }
#pragma unroll
            for (int mf = 0; mf < 4; mf++)
#pragma unroll
                for (int nf = 0; nf < 4; nf++) {
                    mma8(acc[mf][nf], aH[mf], bH[nf]);
                    mma8(acc[mf][nf], aH[mf], bL[nf]);
                    mma8(acc[mf][nf], aL[mf], bH[nf]);
                }
        }
        __syncthreads();
        load_chunk(c + 2);
    }

#pragma unroll
    for (int mf = 0; mf < 4; mf++) {
#pragma unroll
        for (int nf = 0; nf < 4; nf++) {
            int m = m0 + wm * 64 + mf * 16 + grp;
            int n = n0 + wn * 32 + nf * 8 + tg * 2;
            float b0 = __ldg(bias + n), b1 = __ldg(bias + n + 1);
            float2 v0 = make_float2(acc[mf][nf][0] + b0, acc[mf][nf][1] + b1);
            float2 v1 = make_float2(acc[mf][nf][2] + b0, acc[mf][nf][3] + b1);
            if (MODE == 0) {
                *(float2*)(Cout + (size_t)m * DM_ + n) = v0;
                *(float2*)(Cout + (size_t)(m + 8) * DM_ + n) = v1;
            } else {
                int mat = n >> 10;
                int cc = n & 1023;
                int h = cc >> 6, dd = cc & 63;
                float* dst = (mat == 0) ? g_q : (mat == 1) ? g_k : g_v;
                int bidx = m >> 11;
                int l = m & 2047;
                *(float2*)(dst + (((size_t)(bidx * H_ + h)) * L_ + l) * DH_ + dd) = v0;
                *(float2*)(dst + (((size_t)(bidx * H_ + h)) * L_ + l + 8) * DH_ + dd) = v1;
            }
        }
    }
}

// ---------------------------------------------------------------------------
// Fused attention (R10-proven): 128 q-rows/CTA, 64-key tiles.
//  - scores: FFMA2; e -> gmem (fp32) + sP (tf32-rounded)
//  - AV: mma.sync tf32 on P x V (V rna-rounded at stage for unbiased error)
//  - epilogue: hout written PRE-SPLIT to g_hhi/g_hlo (kills decomp pass)
//  - fused rescale of this CTA's attn rows
// ---------------------------------------------------------------------------
#define SQT_F 8448
#define SKT_F 4352
#define SV_F  4352
#define SP_F  8704
#define ATTN_SMEM_FLOATS (SQT_F + SKT_F + SV_F + SP_F + 128)
#define ATTN_SMEM_BYTES  (ATTN_SMEM_FLOATS * 4)

__global__ __launch_bounds__(256, 2) void attn_kernel(float* __restrict__ attn_out)
{
    extern __shared__ float sm[];
    float* sqT = sm;                          // [d][row] stride 132
    float* skT = sm + SQT_F;                  // [d][key] stride 68
    float* sv  = sm + SQT_F + SKT_F;          // [k][dim] stride 68 (tf32)
    float* sP  = sm + SQT_F + SKT_F + SV_F;   // [row][key] stride 68 (tf32)
    float* srow = sP + SP_F;                  // [128]

    const int tid = threadIdx.x;
    const int bh = blockIdx.y;
    const int q0 = blockIdx.x * 128;
    const float* Q = g_q + (size_t)bh * L_ * DH_;
    const float* K = g_k + (size_t)bh * L_ * DH_;
    const float* V = g_v + (size_t)bh * L_ * DH_;
    float* attn = attn_out + (size_t)bh * L_ * L_;

    {
        int lr = tid >> 1;
        int c0 = (tid & 1) * 32;
#pragma unroll
        for (int w = 0; w < 8; w++) {
            float4 qv = *(const float4*)(Q + (size_t)(q0 + lr) * DH_ + c0 + w * 4);
            sqT[(c0 + w * 4 + 0) * 132 + lr] = qv.x;
            sqT[(c0 + w * 4 + 1) * 132 + lr] = qv.y;
            sqT[(c0 + w * 4 + 2) * 132 + lr] = qv.z;
            sqT[(c0 + w * 4 + 3) * 132 + lr] = qv.w;
        }
    }

    const int ty = tid >> 4;   // score rows ty*8 .. ty*8+7
    const int tx = tid & 15;   // score keys tx*4 .. tx*4+3
    const int wid = tid >> 5;
    const int lane = tid & 31;
    const int grp = lane >> 2;
    const int tg = lane & 3;
    const int mq = wid & 3;    // AV q-group of 32 rows
    const int dh = wid >> 2;   // AV d-half of 32 dims

    float facc[2][4][4];
#pragma unroll
    for (int mf = 0; mf < 2; mf++)
#pragma unroll
        for (int nf = 0; nf < 4; nf++)
#pragma unroll
            for (int e = 0; e < 4; e++) facc[mf][nf][e] = 0.f;

    float rsum[8];
#pragma unroll
    for (int i = 0; i < 8; i++) rsum[i] = 0.f;

    const int klr = tid >> 2;
    const int kc  = tid & 3;

    for (int kt = 0; kt < L_ / 64; kt++) {
        const int k0g = kt * 64;
#pragma unroll
        for (int jj = 0; jj < 4; jj++) {
            int d0 = kc * 4 + jj * 16;
            float4 kv = *(const float4*)(K + (size_t)(k0g + klr) * DH_ + d0);
            skT[(d0 + 0) * 68 + klr] = kv.x;
            skT[(d0 + 1) * 68 + klr] = kv.y;
            skT[(d0 + 2) * 68 + klr] = kv.z;
            skT[(d0 + 3) * 68 + klr] = kv.w;
            int vd = kc * 16 + jj * 4;
            float4 vv = *(const float4*)(V + (size_t)(k0g + klr) * DH_ + vd);
            // unbiased tf32 rounding for the AV MMA operand
            vv.x = tf32rna(vv.x); vv.y = tf32rna(vv.y);
            vv.z = tf32rna(vv.z); vv.w = tf32rna(vv.w);
            *(float4*)&sv[klr * 68 + vd] = vv;
        }
        __syncthreads();

        // ---- scores (FFMA2) ----
        unsigned long long s[4][4];
#pragma unroll
        for (int p = 0; p < 4; p++)
#pragma unroll
            for (int j = 0; j < 4; j++) s[p][j] = 0ull;

#pragma unroll 4
        for (int d = 0; d < 64; d++) {
            ulonglong2 qa = *(const ulonglong2*)&sqT[d * 132 + ty * 8];
            ulonglong2 qb = *(const ulonglong2*)&sqT[d * 132 + ty * 8 + 4];
            float4 kf = *(const float4*)&skT[d * 68 + tx * 4];
            float kj[4] = {kf.x, kf.y, kf.z, kf.w};
#pragma unroll
            for (int j = 0; j < 4; j++) {
                unsigned long long kk = pk2(kj[j], kj[j]);
                fma2(s[0][j], qa.x, kk);
                fma2(s[1][j], qa.y, kk);
                fma2(s[2][j], qb.x, kk);
                fma2(s[3][j], qb.y, kk);
            }
        }

        float ev[8][4];
#pragma unroll
        for (int p = 0; p < 4; p++)
#pragma unroll
            for (int j = 0; j < 4; j++) {
                float2 u = upk2(s[p][j]);
                ev[2 * p + 0][j] = __expf(u.x * 0.125f);
                ev[2 * p + 1][j] = __expf(u.y * 0.125f);
            }
#pragma unroll
        for (int i = 0; i < 8; i++) {
            float ls = ev[i][0] + ev[i][1] + ev[i][2] + ev[i][3];
#pragma unroll
            for (int off = 1; off < 16; off <<= 1)
                ls += __shfl_xor_sync(0xffffffffu, ls, off);
            rsum[i] += ls;
            float4 e4 = make_float4(ev[i][0], ev[i][1], ev[i][2], ev[i][3]);
            *(float4*)(attn + (size_t)(q0 + ty * 8 + i) * L_ + k0g + tx * 4) = e4;
            float4 e4r = make_float4(tf32rna(e4.x), tf32rna(e4.y),
                                     tf32rna(e4.z), tf32rna(e4.w));
            *(float4*)&sP[(ty * 8 + i) * 68 + tx * 4] = e4r;
        }

        __syncthreads();

        // ---- AV on the tensor pipe ----
#pragma unroll
        for (int k8 = 0; k8 < 8; k8++) {
            const int kk = k8 * 8;
            float a0[4], a1[4];
            const int mr = mq * 32 + grp;
            a0[0] = sP[(mr) * 68 + kk + tg];
            a0[1] = sP[(mr + 8) * 68 + kk + tg];
            a0[2] = sP[(mr) * 68 + kk + tg + 4];
            a0[3] = sP[(mr + 8) * 68 + kk + tg + 4];
            a1[0] = sP[(mr + 16) * 68 + kk + tg];
            a1[1] = sP[(mr + 24) * 68 + kk + tg];
            a1[2] = sP[(mr + 16) * 68 + kk + tg + 4];
            a1[3] = sP[(mr + 24) * 68 + kk + tg + 4];
            float b[4][2];
#pragma unroll
            for (int nf = 0; nf < 4; nf++) {
                int nd = dh * 32 + nf * 8 + grp;
                b[nf][0] = sv[(kk + tg) * 68 + nd];
                b[nf][1] = sv[(kk + tg + 4) * 68 + nd];
            }
#pragma unroll
            for (int nf = 0; nf < 4; nf++) {
                mma8(facc[0][nf], a0, b[nf]);
                mma8(facc[1][nf], a1, b[nf]);
            }
        }
        __syncthreads();
    }

    if (tx == 0) {
#pragma unroll
        for (int i = 0; i < 8; i++) srow[ty * 8 + i] = rsum[i];
    }
    __syncthreads();

    const int bidx = bh >> 4;
    const int h = bh & 15;

    // AV epilogue: normalize + tf32split, write hhi/hlo directly
#pragma unroll
    for (int mf = 0; mf < 2; mf++) {
#pragma unroll
        for (int nf = 0; nf < 4; nf++) {
            int r0 = mq * 32 + mf * 16 + grp;
            int nd = dh * 32 + nf * 8 + tg * 2;
            float i0 = 1.f / srow[r0];
            float i1 = 1.f / srow[r0 + 8];
            size_t base0 = ((size_t)(bidx * L_) + q0 + r0) * DM_ + h * DH_ + nd;
            size_t base1 = base0 + (size_t)8 * DM_;
            float2 sx, sy;
            sx = tf32split(facc[mf][nf][0] * i0);
            sy = tf32split(facc[mf][nf][1] * i0);
            *(float2*)(g_hhi + base0) = make_float2(sx.x, sy.x);
            *(float2*)(g_hlo + base0) = make_float2(sx.y, sy.y);
            sx = tf32split(facc[mf][nf][2] * i1);
            sy = tf32split(facc[mf][nf][3] * i1);
            *(float2*)(g_hhi + base1) = make_float2(sx.x, sy.x);
            *(float2*)(g_hlo + base1) = make_float2(sx.y, sy.y);
        }
    }

    // fused rescale of this CTA's 128 attn rows
#pragma unroll
    for (int i = 0; i < 8; i++) {
        float inv = 1.f / srow[ty * 8 + i];
        float* rowp = attn + (size_t)(q0 + ty * 8 + i) * L_;
#pragma unroll 4
        for (int j = 0; j < 32; j++) {
            float4* p = (float4*)(rowp + j * 64 + tx * 4);
            float4 v = *p;
            v.x *= inv; v.y *= inv; v.z *= inv; v.w *= inv;
            *p = v;
        }
    }
}

// ---------------------------------------------------------------------------
extern "C" void kernel_launch(void* const* d_in, const int* in_sizes, int n_in,
                              void* d_out, int out_size)
{
    (void)in_sizes; (void)n_in; (void)out_size;
    const float* x    = (const float*)d_in[0];
    const float* Wqkv = (const float*)d_in[1];
    const float* bqkv = (const float*)d_in[2];
    const float* Wout = (const float*)d_in[3];
    const float* bout = (const float*)d_in[4];
    float* out  = (float*)d_out;
    float* attn = out + OUT_ELEMS_;

    static int attr_done = 0;
    if (!attr_done) {
        cudaFuncSetAttribute(attn_kernel,
            cudaFuncAttributeMaxDynamicSharedMemorySize, ATTN_SMEM_BYTES);
        cudaFuncSetAttribute(gemm_mma_kernel<0>,
            cudaFuncAttributeMaxDynamicSharedMemorySize, GEMM_SMEM_BYTES);
        cudaFuncSetAttribute(gemm_mma_kernel<1>,
            cudaFuncAttributeMaxDynamicSharedMemorySize, GEMM_SMEM_BYTES);
        attr_done = 1;
    }

    float *xhi, *xlo, *wqhi, *wqlo, *wohi, *wolo, *hhi, *hlo;
    cudaGetSymbolAddress((void**)&xhi,  g_xhi);
    cudaGetSymbolAddress((void**)&xlo,  g_xlo);
    cudaGetSymbolAddress((void**)&wqhi, g_wqhi);
    cudaGetSymbolAddress((void**)&wqlo, g_wqlo);
    cudaGetSymbolAddress((void**)&wohi, g_wohi);
    cudaGetSymbolAddress((void**)&wolo, g_wolo);
    cudaGetSymbolAddress((void**)&hhi,  g_hhi);
    cudaGetSymbolAddress((void**)&hlo,  g_hlo);

    // operand decompositions
    decomp_kernel<<<OUT_ELEMS_ / 4 / 256, 256>>>(x, xhi, xlo);
    decomp_t_kernel<<<dim3(N3_ / 32, DM_ / 32), 256>>>(Wqkv, wqhi, wqlo, DM_, N3_);
    decomp_t_kernel<<<dim3(DM_ / 32, DM_ / 32), 256>>>(Wout, wohi, wolo, DM_, DM_);

    // QKV projection
    gemm_mma_kernel<1><<<dim3(N3_ / 128, (B_ * L_) / 128), 256, GEMM_SMEM_BYTES>>>(
        xhi, xlo, wqhi, wqlo, bqkv, nullptr);

    // attention (AV on tensor pipe, hout pre-split) + fused rescale
    attn_kernel<<<dim3(L_ / 128, BH_), 256, ATTN_SMEM_BYTES>>>(attn);

    // out projection (reads pre-split hhi/hlo straight from attn)
    gemm_mma_kernel<0><<<dim3(DM_ / 128, (B_ * L_) / 128), 256, GEMM_SMEM_BYTES>>>(
        hhi, hlo, wohi, wolo, bout, out);
}

// round 12
// speedup vs baseline: 1.4852x; 1.0161x over previous
#include <cuda_runtime.h>
#include <cstdint>

#define B_ 4
#define L_ 2048
#define H_ 16
#define DH_ 64
#define DM_ 1024
#define N3_ 3072
#define BH_ (B_*H_)
#define OUT_ELEMS_ (B_*L_*DM_)   // 8388608

// Scratch (device globals: allocation-free per harness rules)
__device__ float g_q[BH_*L_*DH_];     // fp32
__device__ float g_khi[BH_*L_*DH_];   // K pre-split tf32 hi/lo (gemm epilogue)
__device__ float g_klo[BH_*L_*DH_];
__device__ float g_v[BH_*L_*DH_];     // V pre-rounded to tf32 (rna)

// tf32 hi/lo decompositions for projections
__device__ float g_xhi[B_*L_*DM_];
__device__ float g_xlo[B_*L_*DM_];
__device__ float g_wqhi[N3_*DM_];    // [n][k] (transposed W_qkv)
__device__ float g_wqlo[N3_*DM_];
__device__ float g_wohi[DM_*DM_];    // [n][k] (transposed W_out)
__device__ float g_wolo[DM_*DM_];
__device__ float g_hhi[B_*L_*DM_];   // attn writes hout pre-split
__device__ float g_hlo[B_*L_*DM_];

// ---------------------------------------------------------------------------
// Helpers
// ---------------------------------------------------------------------------
__device__ __forceinline__ uint32_t smem_u32(const void* p) {
    uint32_t a;
    asm("{ .reg .u64 t; cvta.to.shared.u64 t, %1; cvt.u32.u64 %0, t; }"
        : "=r"(a) : "l"(p));
    return a;
}
__device__ __forceinline__ void cpa16(uint32_t dst, const float* src) {
    asm volatile("cp.async.cg.shared.global [%0], [%1], 16;" :: "r"(dst), "l"(src));
}
__device__ __forceinline__ float2 tf32split(float a) {
    uint32_t hb;
    asm("cvt.rna.tf32.f32 %0, %1;" : "=r"(hb) : "f"(a));
    float hi = __uint_as_float(hb);
    float lo = a - hi;
    uint32_t lb;
    asm("cvt.rna.tf32.f32 %0, %1;" : "=r"(lb) : "f"(lo));
    return make_float2(hi, __uint_as_float(lb));
}
__device__ __forceinline__ float tf32rna(float a) {
    uint32_t b;
    asm("cvt.rna.tf32.f32 %0, %1;" : "=r"(b) : "f"(a));
    return __uint_as_float(b);
}
// m16n8k8 tf32 MMA (baseline PTX, works on compute_103)
__device__ __forceinline__ void mma8(float c[4], const float a[4], const float b[2]) {
    asm volatile(
        "mma.sync.aligned.m16n8k8.row.col.f32.tf32.tf32.f32 "
        "{%0,%1,%2,%3}, {%4,%5,%6,%7}, {%8,%9}, {%0,%1,%2,%3};"
        : "+f"(c[0]), "+f"(c[1]), "+f"(c[2]), "+f"(c[3])
        : "r"(__float_as_uint(a[0])), "r"(__float_as_uint(a[1])),
          "r"(__float_as_uint(a[2])), "r"(__float_as_uint(a[3])),
          "r"(__float_as_uint(b[0])), "r"(__float_as_uint(b[1])));
}

// ---------------------------------------------------------------------------
// Decomposition kernels
// ---------------------------------------------------------------------------
__global__ __launch_bounds__(256) void decomp_kernel(
    const float* __restrict__ src, float* __restrict__ hi, float* __restrict__ lo)
{
    int i = blockIdx.x * 256 + threadIdx.x;
    float4 v = ((const float4*)src)[i];
    float2 sx = tf32split(v.x), sy = tf32split(v.y);
    float2 sz = tf32split(v.z), sw = tf32split(v.w);
    ((float4*)hi)[i] = make_float4(sx.x, sy.x, sz.x, sw.x);
    ((float4*)lo)[i] = make_float4(sx.y, sy.y, sz.y, sw.y);
}

// W[k][n] -> hi/lo [n][k]
__global__ __launch_bounds__(256) void decomp_t_kernel(
    const float* __restrict__ src, float* __restrict__ dhi, float* __restrict__ dlo,
    int K, int N)
{
    __shared__ float t[32][33];
    int k0 = blockIdx.y * 32, n0 = blockIdx.x * 32;
    int r = threadIdx.x >> 3;
    int c4 = (threadIdx.x & 7) * 4;
    float4 v = *(const float4*)(src + (size_t)(k0 + r) * N + n0 + c4);
    t[r][c4 + 0] = v.x; t[r][c4 + 1] = v.y; t[r][c4 + 2] = v.z; t[r][c4 + 3] = v.w;
    __syncthreads();
    float2 s0 = tf32split(t[c4 + 0][r]);
    float2 s1 = tf32split(t[c4 + 1][r]);
    float2 s2 = tf32split(t[c4 + 2][r]);
    float2 s3 = tf32split(t[c4 + 3][r]);
    *(float4*)(dhi + (size_t)(n0 + r) * K + k0 + c4) =
        make_float4(s0.x, s1.x, s2.x, s3.x);
    *(float4*)(dlo + (size_t)(n0 + r) * K + k0 + c4) =
        make_float4(s0.y, s1.y, s2.y, s3.y);
}

// ---------------------------------------------------------------------------
// mma.sync tf32 3x GEMM (R11-proven: k16 chunks, 2 stages, 2 CTA/SM).
// MODE 0: out projection  (C -> Cout[m][n] + bias)
// MODE 1: qkv projection  (q fp32; k split hi/lo; v tf32-rounded)
// ---------------------------------------------------------------------------
#define CH_F 20
#define ARR_F (128 * CH_F)
#define STAGE_F (4 * ARR_F)
#define GEMM_SMEM_BYTES (2 * STAGE_F * 4)   // 81920
#define NCHUNK 64

template <int MODE>
__global__ __launch_bounds__(256, 2) void gemm_mma_kernel(
    const float* __restrict__ Ahi, const float* __restrict__ Alo,
    const float* __restrict__ Bhi, const float* __restrict__ Blo,
    const float* __restrict__ bias, float* __restrict__ Cout)
{
    extern __shared__ float gsm[];
    const uint32_t sbase = smem_u32(gsm);
    const int tid = threadIdx.x;
    const int wid = tid >> 5;
    const int lane = tid & 31;
    const int grp = lane >> 2;
    const int tg = lane & 3;
    const int n0 = blockIdx.x * 128;
    const int m0 = blockIdx.y * 128;

    const int lrow = tid >> 1;
    const int lg = (tid & 1) * 8;

    const float* srcA_hi = Ahi + (size_t)(m0 + lrow) * DM_ + lg;
    const float* srcA_lo = Alo + (size_t)(m0 + lrow) * DM_ + lg;
    const float* srcB_hi = Bhi + (size_t)(n0 + lrow) * DM_ + lg;
    const float* srcB_lo = Blo + (size_t)(n0 + lrow) * DM_ + lg;

    auto load_chunk = [&](int c) {
        if (c < NCHUNK) {
            const uint32_t sb = sbase + ((c & 1) * STAGE_F) * 4;
            const uint32_t dbase = sb + (lrow * CH_F + lg) * 4;
            const int k0 = c * 16;
            cpa16(dbase + 0 * ARR_F * 4,      srcA_hi + k0);
            cpa16(dbase + 0 * ARR_F * 4 + 16, srcA_hi + k0 + 4);
            cpa16(dbase + 1 * ARR_F * 4,      srcA_lo + k0);
            cpa16(dbase + 1 * ARR_F * 4 + 16, srcA_lo + k0 + 4);
            cpa16(dbase + 2 * ARR_F * 4,      srcB_hi + k0);
            cpa16(dbase + 2 * ARR_F * 4 + 16, srcB_hi + k0 + 4);
            cpa16(dbase + 3 * ARR_F * 4,      srcB_lo + k0);
            cpa16(dbase + 3 * ARR_F * 4 + 16, srcB_lo + k0 + 4);
        }
        asm volatile("cp.async.commit_group;" ::: "memory");
    };

    const int wm = wid & 1;
    const int wn = wid >> 1;

    float acc[4][4][4];
#pragma unroll
    for (int mf = 0; mf < 4; mf++)
#pragma unroll
        for (int nf = 0; nf < 4; nf++)
#pragma unroll
            for (int e = 0; e < 4; e++) acc[mf][nf][e] = 0.f;

    load_chunk(0);
    load_chunk(1);

    for (int c = 0; c < NCHUNK; c++) {
        asm volatile("cp.async.wait_group 1;" ::: "memory");
        __syncthreads();

        const float* sb = gsm + (c & 1) * STAGE_F;
        const float* sAhi = sb;
        const float* sAlo = sb + ARR_F;
        const float* sBhi = sb + 2 * ARR_F;
        const float* sBlo = sb + 3 * ARR_F;

#pragma unroll
        for (int k8 = 0; k8 < 2; k8++) {
            const int kk = k8 * 8;
            float aH[4][4], aL[4][4];
#pragma unroll
            for (int mf = 0; mf < 4; mf++) {
                int mr = wm * 64 + mf * 16 + grp;
                aH[mf][0] = sAhi[(mr) * CH_F + kk + tg];
                aH[mf][1] = sAhi[(mr + 8) * CH_F + kk + tg];
                aH[mf][2] = sAhi[(mr) * CH_F + kk + tg + 4];
                aH[mf][3] = sAhi[(mr + 8) * CH_F + kk + tg + 4];
                aL[mf][0] = sAlo[(mr) * CH_F + kk + tg];
                aL[mf][1] = sAlo[(mr + 8) * CH_F + kk + tg];
                aL[mf][2] = sAlo[(mr) * CH_F + kk + tg + 4];
                aL[mf][3] = sAlo[(mr + 8) * CH_F + kk + tg + 4];
            }
            float bH[4][2], bL[4][2];
#pragma unroll
            for (int nf = 0; nf < 4; nf++) {
                int nr = wn * 32 + nf * 8 + grp;
                bH[nf][0] = sBhi[nr * CH_F + kk + tg];
                bH[nf][1] = sBhi[nr * CH_F + kk + tg + 4];
                bL[nf][0] = sBlo[nr * CH_F + kk + tg];
                bL[nf][1] = sBlo[nr * CH_F + kk + tg + 4];
            }
#pragma unroll
            for (int mf = 0; mf < 4; mf++)
#pragma unroll
                for (int nf = 0; nf < 4; nf++) {
                    mma8(acc[mf][nf], aH[mf], bH[nf]);
                    mma8(acc[mf][nf], aH[mf], bL[nf]);
                    mma8(acc[mf][nf], aL[mf], bH[nf]);
                }
        }
        __syncthreads();
        load_chunk(c + 2);
    }

#pragma unroll
    for (int mf = 0; mf < 4; mf++) {
#pragma unroll
        for (int nf = 0; nf < 4; nf++) {
            int m = m0 + wm * 64 + mf * 16 + grp;
            int n = n0 + wn * 32 + nf * 8 + tg * 2;
            float b0 = __ldg(bias + n), b1 = __ldg(bias + n + 1);
            float2 v0 = make_float2(acc[mf][nf][0] + b0, acc[mf][nf][1] + b1);
            float2 v1 = make_float2(acc[mf][nf][2] + b0, acc[mf][nf][3] + b1);
            if (MODE == 0) {
                *(float2*)(Cout + (size_t)m * DM_ + n) = v0;
                *(float2*)(Cout + (size_t)(m + 8) * DM_ + n) = v1;
            } else {
                int mat = n >> 10;
                int cc = n & 1023;
                int h = cc >> 6, dd = cc & 63;
                int bidx = m >> 11;
                int l = m & 2047;
                size_t i0 = (((size_t)(bidx * H_ + h)) * L_ + l) * DH_ + dd;
                size_t i1 = (((size_t)(bidx * H_ + h)) * L_ + l + 8) * DH_ + dd;
                if (mat == 0) {
                    *(float2*)(g_q + i0) = v0;
                    *(float2*)(g_q + i1) = v1;
                } else if (mat == 1) {
                    float2 sx = tf32split(v0.x), sy = tf32split(v0.y);
                    *(float2*)(g_khi + i0) = make_float2(sx.x, sy.x);
                    *(float2*)(g_klo + i0) = make_float2(sx.y, sy.y);
                    sx = tf32split(v1.x); sy = tf32split(v1.y);
                    *(float2*)(g_khi + i1) = make_float2(sx.x, sy.x);
                    *(float2*)(g_klo + i1) = make_float2(sx.y, sy.y);
                } else {
                    *(float2*)(g_v + i0) = make_float2(tf32rna(v0.x), tf32rna(v0.y));
                    *(float2*)(g_v + i1) = make_float2(tf32rna(v1.x), tf32rna(v1.y));
                }
            }
        }
    }
}

// ---------------------------------------------------------------------------
// Attention, fully tensor-pipe: 128 q-rows/CTA, 64-key tiles, 8 warps.
// Warp tile: 16 rows x 64 keys.
//  - scores: 3xTF32 mma (Q fp32 in smem, split in regs; K pre-split hi/lo)
//  - exp + rowsum in C-fragment layout; e -> gmem fp32
//  - C-frag -> AV A-frag via quad shuffles (no sP, no extra sync)
//  - AV: mma tf32 with V (pre-rounded) from smem
//  - epilogue: hout pre-split to g_hhi/g_hlo; fused rescale of attn rows
// smem: sq[128][68] + sKhi/sKlo/sv[64][68] + srow[128] = 21888 f = 87.5 KB
// ---------------------------------------------------------------------------
#define SQ_F (128 * 68)
#define SK_F (64 * 68)
#define ATTN_SMEM_FLOATS (SQ_F + 3 * SK_F + 128)
#define ATTN_SMEM_BYTES  (ATTN_SMEM_FLOATS * 4)   // 87552

__global__ __launch_bounds__(256, 2) void attn_kernel(float* __restrict__ attn_out)
{
    extern __shared__ float sm[];
    float* sq   = sm;                 // [row][d] stride 68 fp32
    float* sKhi = sm + SQ_F;          // [key][d] stride 68
    float* sKlo = sKhi + SK_F;
    float* sv   = sKlo + SK_F;        // [key][dim] stride 68 (tf32)
    float* srow = sv + SK_F;          // [128]
    const uint32_t sb = smem_u32(sm);

    const int tid = threadIdx.x;
    const int wid = tid >> 5;
    const int lane = tid & 31;
    const int grp = lane >> 2;
    const int tg = lane & 3;
    const int mr = wid * 16 + grp;    // this lane's base q-row (and +8)

    const int bh = blockIdx.y;
    const int q0 = blockIdx.x * 128;
    const size_t base = (size_t)bh * L_ * DH_;
    float* attn = attn_out + (size_t)bh * L_ * L_;

    // Q tile load (cp.async, one-time): 128x64 fp32
    {
        int lr = tid >> 1;
        int lc = (tid & 1) * 32;
        const float* src = g_q + base + (size_t)(q0 + lr) * DH_ + lc;
        uint32_t dst = sb + (lr * 68 + lc) * 4;
#pragma unroll
        for (int j = 0; j < 8; j++) cpa16(dst + j * 16, src + j * 4);
        asm volatile("cp.async.commit_group;" ::: "memory");
    }

    float o[8][4];
#pragma unroll
    for (int j = 0; j < 8; j++)
#pragma unroll
        for (int e = 0; e < 4; e++) o[j][e] = 0.f;
    float rsum0 = 0.f, rsum1 = 0.f;

    const int klr = tid >> 2;          // 0..63 key row
    const int kc = (tid & 3) * 16;     // col group

    for (int kt = 0; kt < L_ / 64; kt++) {
        const int k0g = kt * 64;
        // K hi/lo + V tile loads (cp.async)
        {
            const float* skh = g_khi + base + (size_t)(k0g + klr) * DH_ + kc;
            const float* skl = g_klo + base + (size_t)(k0g + klr) * DH_ + kc;
            const float* svv = g_v  + base + (size_t)(k0g + klr) * DH_ + kc;
            uint32_t d0 = sb + (SQ_F + klr * 68 + kc) * 4;
#pragma unroll
            for (int j = 0; j < 4; j++) {
                cpa16(d0 + j * 16,                 skh + j * 4);
                cpa16(d0 + SK_F * 4 + j * 16,      skl + j * 4);
                cpa16(d0 + 2 * SK_F * 4 + j * 16,  svv + j * 4);
            }
            asm volatile("cp.async.commit_group;" ::: "memory");
            asm volatile("cp.async.wait_group 0;" ::: "memory");
        }
        __syncthreads();

        // ---- scores: 3xTF32 mma, warp tile 16 rows x 64 keys ----
        float c[8][4];
#pragma unroll
        for (int nf = 0; nf < 8; nf++)
#pragma unroll
            for (int e = 0; e < 4; e++) c[nf][e] = 0.f;

#pragma unroll
        for (int k8 = 0; k8 < 8; k8++) {
            const int kk = k8 * 8;
            float af[4], aH[4], aL[4];
            af[0] = sq[(mr) * 68 + kk + tg];
            af[1] = sq[(mr + 8) * 68 + kk + tg];
            af[2] = sq[(mr) * 68 + kk + tg + 4];
            af[3] = sq[(mr + 8) * 68 + kk + tg + 4];
#pragma unroll
            for (int e = 0; e < 4; e++) {
                aH[e] = tf32rna(af[e]);
                aL[e] = tf32rna(af[e] - aH[e]);
            }
#pragma unroll
            for (int nf = 0; nf < 8; nf++) {
                int nr = nf * 8 + grp;
                float bH[2], bL[2];
                bH[0] = sKhi[nr * 68 + kk + tg];
                bH[1] = sKhi[nr * 68 + kk + tg + 4];
                bL[0] = sKlo[nr * 68 + kk + tg];
                bL[1] = sKlo[nr * 68 + kk + tg + 4];
                mma8(c[nf], aH, bH);
                mma8(c[nf], aL, bH);
                mma8(c[nf], aH, bL);
            }
        }

        // ---- exp + rowsum + gmem store (fragment layout) ----
        {
            float rs0 = 0.f, rs1 = 0.f;
#pragma unroll
            for (int nf = 0; nf < 8; nf++) {
                float e0 = __expf(c[nf][0] * 0.125f);
                float e1 = __expf(c[nf][1] * 0.125f);
                float e2 = __expf(c[nf][2] * 0.125f);
                float e3 = __expf(c[nf][3] * 0.125f);
                c[nf][0] = e0; c[nf][1] = e1; c[nf][2] = e2; c[nf][3] = e3;
                rs0 += e0 + e1;
                rs1 += e2 + e3;
                int n = k0g + nf * 8 + tg * 2;
                *(float2*)(attn + (size_t)(q0 + mr) * L_ + n) = make_float2(e0, e1);
                *(float2*)(attn + (size_t)(q0 + mr + 8) * L_ + n) = make_float2(e2, e3);
            }
            rs0 += __shfl_xor_sync(0xffffffffu, rs0, 1);
            rs0 += __shfl_xor_sync(0xffffffffu, rs0, 2);
            rs1 += __shfl_xor_sync(0xffffffffu, rs1, 1);
            rs1 += __shfl_xor_sync(0xffffffffu, rs1, 2);
            rsum0 += rs0;
            rsum1 += rs1;
        }

        // ---- AV: C-frag -> A-frag via quad shuffles, mma with V ----
        const int s1 = (lane & ~3) | (tg >> 1);
        const int s2 = s1 + 2;
        const bool odd = tg & 1;
#pragma unroll
        for (int nf = 0; nf < 8; nf++) {
            float v0 = __shfl_sync(0xffffffffu, c[nf][0], s1);
            float v1 = __shfl_sync(0xffffffffu, c[nf][1], s1);
            float v2 = __shfl_sync(0xffffffffu, c[nf][2], s1);
            float v3 = __shfl_sync(0xffffffffu, c[nf][3], s1);
            float w0 = __shfl_sync(0xffffffffu, c[nf][0], s2);
            float w1 = __shfl_sync(0xffffffffu, c[nf][1], s2);
            float w2 = __shfl_sync(0xffffffffu, c[nf][2], s2);
            float w3 = __shfl_sync(0xffffffffu, c[nf][3], s2);
            float a[4];
            a[0] = tf32rna(odd ? v1 : v0);
            a[1] = tf32rna(odd ? v3 : v2);
            a[2] = tf32rna(odd ? w1 : w0);
            a[3] = tf32rna(odd ? w3 : w2);
            const int kk = nf * 8;
#pragma unroll
            for (int j = 0; j < 8; j++) {
                float b[2];
                b[0] = sv[(kk + tg) * 68 + j * 8 + grp];
                b[1] = sv[(kk + tg + 4) * 68 + j * 8 + grp];
                mma8(o[j], a, b);
            }
        }
        __syncthreads();   // all reads done before next tile's cp.async
    }

    if (tg == 0) {
        srow[wid * 16 + grp] = rsum0;
        srow[wid * 16 + grp + 8] = rsum1;
    }
    __syncthreads();

    const int bidx = bh >> 4;
    const int h = bh & 15;

    // O epilogue: normalize + tf32split -> g_hhi/g_hlo
    {
        float i0 = 1.f / srow[wid * 16 + grp];
        float i1 = 1.f / srow[wid * 16 + grp + 8];
        size_t r0 = ((size_t)(bidx * L_) + q0 + mr) * DM_ + h * DH_;
        size_t r1 = r0 + (size_t)8 * DM_;
#pragma unroll
        for (int j = 0; j < 8; j++) {
            int nd = j * 8 + tg * 2;
            float2 sx = tf32split(o[j][0] * i0);
            float2 sy = tf32split(o[j][1] * i0);
            *(float2*)(g_hhi + r0 + nd) = make_float2(sx.x, sy.x);
            *(float2*)(g_hlo + r0 + nd) = make_float2(sx.y, sy.y);
            sx = tf32split(o[j][2] * i1);
            sy = tf32split(o[j][3] * i1);
            *(float2*)(g_hhi + r1 + nd) = make_float2(sx.x, sy.x);
            *(float2*)(g_hlo + r1 + nd) = make_float2(sx.y, sy.y);
        }
    }

    // fused rescale of this CTA's 128 attn rows
    {
        const int ty = tid >> 4;
        const int tx = tid & 15;
#pragma unroll
        for (int i = 0; i < 8; i++) {
            float inv = 1.f / srow[ty * 8 + i];
            float* rowp = attn + (size_t)(q0 + ty * 8 + i) * L_;
#pragma unroll 4
            for (int j = 0; j < 32; j++) {
                float4* p = (float4*)(rowp + j * 64 + tx * 4);
                float4 v = *p;
                v.x *= inv; v.y *= inv; v.z *= inv; v.w *= inv;
                *p = v;
            }
        }
    }
}

// ---------------------------------------------------------------------------
extern "C" void kernel_launch(void* const* d_in, const int* in_sizes, int n_in,
                              void* d_out, int out_size)
{
    (void)in_sizes; (void)n_in; (void)out_size;
    const float* x    = (const float*)d_in[0];
    const float* Wqkv = (const float*)d_in[1];
    const float* bqkv = (const float*)d_in[2];
    const float* Wout = (const float*)d_in[3];
    const float* bout = (const float*)d_in[4];
    float* out  = (float*)d_out;
    float* attn = out + OUT_ELEMS_;

    static int attr_done = 0;
    if (!attr_done) {
        cudaFuncSetAttribute(attn_kernel,
            cudaFuncAttributeMaxDynamicSharedMemorySize, ATTN_SMEM_BYTES);
        cudaFuncSetAttribute(gemm_mma_kernel<0>,
            cudaFuncAttributeMaxDynamicSharedMemorySize, GEMM_SMEM_BYTES);
        cudaFuncSetAttribute(gemm_mma_kernel<1>,
            cudaFuncAttributeMaxDynamicSharedMemorySize, GEMM_SMEM_BYTES);
        attr_done = 1;
    }

    float *xhi, *xlo, *wqhi, *wqlo, *wohi, *wolo, *hhi, *hlo;
    cudaGetSymbolAddress((void**)&xhi,  g_xhi);
    cudaGetSymbolAddress((void**)&xlo,  g_xlo);
    cudaGetSymbolAddress((void**)&wqhi, g_wqhi);
    cudaGetSymbolAddress((void**)&wqlo, g_wqlo);
    cudaGetSymbolAddress((void**)&wohi, g_wohi);
    cudaGetSymbolAddress((void**)&wolo, g_wolo);
    cudaGetSymbolAddress((void**)&hhi,  g_hhi);
    cudaGetSymbolAddress((void**)&hlo,  g_hlo);

    // operand decompositions
    decomp_kernel<<<OUT_ELEMS_ / 4 / 256, 256>>>(x, xhi, xlo);
    decomp_t_kernel<<<dim3(N3_ / 32, DM_ / 32), 256>>>(Wqkv, wqhi, wqlo, DM_, N3_);
    decomp_t_kernel<<<dim3(DM_ / 32, DM_ / 32), 256>>>(Wout, wohi, wolo, DM_, DM_);

    // QKV projection (q fp32, k split hi/lo, v tf32-rounded)
    gemm_mma_kernel<1><<<dim3(N3_ / 128, (B_ * L_) / 128), 256, GEMM_SMEM_BYTES>>>(
        xhi, xlo, wqhi, wqlo, bqkv, nullptr);

    // attention (scores + AV on tensor pipe) + fused rescale
    attn_kernel<<<dim3(L_ / 128, BH_), 256, ATTN_SMEM_BYTES>>>(attn);

    // out projection (reads pre-split hhi/hlo straight from attn)
    gemm_mma_kernel<0><<<dim3(DM_ / 128, (B_ * L_) / 128), 256, GEMM_SMEM_BYTES>>>(
        hhi, hlo, wohi, wolo, bout, out);
}

// round 14
// speedup vs baseline: 1.4947x; 1.0064x over previous
#include <cuda_runtime.h>
#include <cstdint>

#define B_ 4
#define L_ 2048
#define H_ 16
#define DH_ 64
#define DM_ 1024
#define N3_ 3072
#define BH_ (B_*H_)
#define OUT_ELEMS_ (B_*L_*DM_)   // 8388608

// Scratch (device globals: allocation-free per harness rules)
__device__ float g_q[BH_*L_*DH_];     // fp32
__device__ float g_k[BH_*L_*DH_];     // fp32 (split to tf32 hi/lo in regs)
__device__ float g_v[BH_*L_*DH_];     // pre-rounded tf32 (rna)

// tf32 hi/lo decompositions for projections
__device__ float g_xhi[B_*L_*DM_];
__device__ float g_xlo[B_*L_*DM_];
__device__ float g_wqhi[N3_*DM_];    // [n][k] (transposed W_qkv)
__device__ float g_wqlo[N3_*DM_];
__device__ float g_wohi[DM_*DM_];    // [n][k] (transposed W_out)
__device__ float g_wolo[DM_*DM_];
__device__ float g_hhi[B_*L_*DM_];   // attn writes hout pre-split
__device__ float g_hlo[B_*L_*DM_];

// ---------------------------------------------------------------------------
// Helpers
// ---------------------------------------------------------------------------
__device__ __forceinline__ uint32_t smem_u32(const void* p) {
    uint32_t a;
    asm("{ .reg .u64 t; cvta.to.shared.u64 t, %1; cvt.u32.u64 %0, t; }"
        : "=r"(a) : "l"(p));
    return a;
}
__device__ __forceinline__ void cpa16(uint32_t dst, const float* src) {
    asm volatile("cp.async.cg.shared.global [%0], [%1], 16;" :: "r"(dst), "l"(src));
}
__device__ __forceinline__ float2 tf32split(float a) {
    uint32_t hb;
    asm("cvt.rna.tf32.f32 %0, %1;" : "=r"(hb) : "f"(a));
    float hi = __uint_as_float(hb);
    float lo = a - hi;
    uint32_t lb;
    asm("cvt.rna.tf32.f32 %0, %1;" : "=r"(lb) : "f"(lo));
    return make_float2(hi, __uint_as_float(lb));
}
__device__ __forceinline__ float tf32rna(float a) {
    uint32_t b;
    asm("cvt.rna.tf32.f32 %0, %1;" : "=r"(b) : "f"(a));
    return __uint_as_float(b);
}
// m16n8k8 tf32 MMA (baseline PTX, works on compute_103)
__device__ __forceinline__ void mma8(float c[4], const float a[4], const float b[2]) {
    asm volatile(
        "mma.sync.aligned.m16n8k8.row.col.f32.tf32.tf32.f32 "
        "{%0,%1,%2,%3}, {%4,%5,%6,%7}, {%8,%9}, {%0,%1,%2,%3};"
        : "+f"(c[0]), "+f"(c[1]), "+f"(c[2]), "+f"(c[3])
        : "r"(__float_as_uint(a[0])), "r"(__float_as_uint(a[1])),
          "r"(__float_as_uint(a[2])), "r"(__float_as_uint(a[3])),
          "r"(__float_as_uint(b[0])), "r"(__float_as_uint(b[1])));
}

// ---------------------------------------------------------------------------
// Decomposition kernels
// ---------------------------------------------------------------------------
__global__ __launch_bounds__(256) void decomp_kernel(
    const float* __restrict__ src, float* __restrict__ hi, float* __restrict__ lo)
{
    int i = blockIdx.x * 256 + threadIdx.x;
    float4 v = ((const float4*)src)[i];
    float2 sx = tf32split(v.x), sy = tf32split(v.y);
    float2 sz = tf32split(v.z), sw = tf32split(v.w);
    ((float4*)hi)[i] = make_float4(sx.x, sy.x, sz.x, sw.x);
    ((float4*)lo)[i] = make_float4(sx.y, sy.y, sz.y, sw.y);
}

// W[k][n] -> hi/lo [n][k]
__global__ __launch_bounds__(256) void decomp_t_kernel(
    const float* __restrict__ src, float* __restrict__ dhi, float* __restrict__ dlo,
    int K, int N)
{
    __shared__ float t[32][33];
    int k0 = blockIdx.y * 32, n0 = blockIdx.x * 32;
    int r = threadIdx.x >> 3;
    int c4 = (threadIdx.x & 7) * 4;
    float4 v = *(const float4*)(src + (size_t)(k0 + r) * N + n0 + c4);
    t[r][c4 + 0] = v.x; t[r][c4 + 1] = v.y; t[r][c4 + 2] = v.z; t[r][c4 + 3] = v.w;
    __syncthreads();
    float2 s0 = tf32split(t[c4 + 0][r]);
    float2 s1 = tf32split(t[c4 + 1][r]);
    float2 s2 = tf32split(t[c4 + 2][r]);
    float2 s3 = tf32split(t[c4 + 3][r]);
    *(float4*)(dhi + (size_t)(n0 + r) * K + k0 + c4) =
        make_float4(s0.x, s1.x, s2.x, s3.x);
    *(float4*)(dlo + (size_t)(n0 + r) * K + k0 + c4) =
        make_float4(s0.y, s1.y, s2.y, s3.y);
}

// ---------------------------------------------------------------------------
// mma.sync tf32 3x GEMM (R12-proven exactly: k16 chunks, CH_F=20, 2 stages,
// 80 KB smem, 2 CTA/SM).  CH_F must keep row stride a multiple of 16 bytes
// for cp.async alignment (20 floats = 80 B OK; 18 floats = 72 B FAULTS).
// MODE 0: out projection  (C -> Cout[m][n] + bias)
// MODE 1: qkv projection  (q,k fp32; v tf32-rounded)
// ---------------------------------------------------------------------------
#define CH_F 20
#define ARR_F (128 * CH_F)
#define STAGE_F (4 * ARR_F)
#define GEMM_SMEM_BYTES (2 * STAGE_F * 4)   // 81920
#define NCHUNK 64

template <int MODE>
__global__ __launch_bounds__(256, 2) void gemm_mma_kernel(
    const float* __restrict__ Ahi, const float* __restrict__ Alo,
    const float* __restrict__ Bhi, const float* __restrict__ Blo,
    const float* __restrict__ bias, float* __restrict__ Cout)
{
    extern __shared__ float gsm[];
    const uint32_t sbase = smem_u32(gsm);
    const int tid = threadIdx.x;
    const int wid = tid >> 5;
    const int lane = tid & 31;
    const int grp = lane >> 2;
    const int tg = lane & 3;
    const int n0 = blockIdx.x * 128;
    const int m0 = blockIdx.y * 128;

    const int lrow = tid >> 1;
    const int lg = (tid & 1) * 8;

    const float* srcA_hi = Ahi + (size_t)(m0 + lrow) * DM_ + lg;
    const float* srcA_lo = Alo + (size_t)(m0 + lrow) * DM_ + lg;
    const float* srcB_hi = Bhi + (size_t)(n0 + lrow) * DM_ + lg;
    const float* srcB_lo = Blo + (size_t)(n0 + lrow) * DM_ + lg;

    auto load_chunk = [&](int c) {
        if (c < NCHUNK) {
            const uint32_t sb = sbase + ((c & 1) * STAGE_F) * 4;
            const uint32_t dbase = sb + (lrow * CH_F + lg) * 4;
            const int k0 = c * 16;
            cpa16(dbase + 0 * ARR_F * 4,      srcA_hi + k0);
            cpa16(dbase + 0 * ARR_F * 4 + 16, srcA_hi + k0 + 4);
            cpa16(dbase + 1 * ARR_F * 4,      srcA_lo + k0);
            cpa16(dbase + 1 * ARR_F * 4 + 16, srcA_lo + k0 + 4);
            cpa16(dbase + 2 * ARR_F * 4,      srcB_hi + k0);
            cpa16(dbase + 2 * ARR_F * 4 + 16, srcB_hi + k0 + 4);
            cpa16(dbase + 3 * ARR_F * 4,      srcB_lo + k0);
            cpa16(dbase + 3 * ARR_F * 4 + 16, srcB_lo + k0 + 4);
        }
        asm volatile("cp.async.commit_group;" ::: "memory");
    };

    const int wm = wid & 1;
    const int wn = wid >> 1;

    float acc[4][4][4];
#pragma unroll
    for (int mf = 0; mf < 4; mf++)
#pragma unroll
        for (int nf = 0; nf < 4; nf++)
#pragma unroll
            for (int e = 0; e < 4; e++) acc[mf][nf][e] = 0.f;

    load_chunk(0);
    load_chunk(1);

    for (int c = 0; c < NCHUNK; c++) {
        asm volatile("cp.async.wait_group 1;" ::: "memory");
        __syncthreads();

        const float* sb = gsm + (c & 1) * STAGE_F;
        const float* sAhi = sb;
        const float* sAlo = sb + ARR_F;
        const float* sBhi = sb + 2 * ARR_F;
        const float* sBlo = sb + 3 * ARR_F;

#pragma unroll
        for (int k8 = 0; k8 < 2; k8++) {
            const int kk = k8 * 8;
            float aH[4][4], aL[4][4];
#pragma unroll
            for (int mf = 0; mf < 4; mf++) {
                int mr = wm * 64 + mf * 16 + grp;
                aH[mf][0] = sAhi[(mr) * CH_F + kk + tg];
                aH[mf][1] = sAhi[(mr + 8) * CH_F + kk + tg];
                aH[mf][2] = sAhi[(mr) * CH_F + kk + tg + 4];
                aH[mf][3] = sAhi[(mr + 8) * CH_F + kk + tg + 4];
                aL[mf][0] = sAlo[(mr) * CH_F + kk + tg];
                aL[mf][1] = sAlo[(mr + 8) * CH_F + kk + tg];
                aL[mf][2] = sAlo[(mr) * CH_F + kk + tg + 4];
                aL[mf][3] = sAlo[(mr + 8) * CH_F + kk + tg + 4];
            }
            float bH[4][2], bL[4][2];
#pragma unroll
            for (int nf = 0; nf < 4; nf++) {
                int nr = wn * 32 + nf * 8 + grp;
                bH[nf][0] = sBhi[nr * CH_F + kk + tg];
                bH[nf][1] = sBhi[nr * CH_F + kk + tg + 4];
                bL[nf][0] = sBlo[nr * CH_F + kk + tg];
                bL[nf][1] = sBlo[nr * CH_F + kk + tg + 4];
            }
#pragma unroll
            for (int mf = 0; mf < 4; mf++)
#pragma unroll
                for (int nf = 0; nf < 4; nf++) {
                    mma8(acc[mf][nf], aH[mf], bH[nf]);
                    mma8(acc[mf][nf], aH[mf], bL[nf]);
                    mma8(acc[mf][nf], aL[mf], bH[nf]);
                }
        }
        __syncthreads();
        load_chunk(c + 2);
    }

#pragma unroll
    for (int mf = 0; mf < 4; mf++) {
#pragma unroll
        for (int nf = 0; nf < 4; nf++) {
            int m = m0 + wm * 64 + mf * 16 + grp;
            int n = n0 + wn * 32 + nf * 8 + tg * 2;
            float b0 = __ldg(bias + n), b1 = __ldg(bias + n + 1);
            float2 v0 = make_float2(acc[mf][nf][0] + b0, acc[mf][nf][1] + b1);
            float2 v1 = make_float2(acc[mf][nf][2] + b0, acc[mf][nf][3] + b1);
            if (MODE == 0) {
                *(float2*)(Cout + (size_t)m * DM_ + n) = v0;
                *(float2*)(Cout + (size_t)(m + 8) * DM_ + n) = v1;
            } else {
                int mat = n >> 10;
                int cc = n & 1023;
                int h = cc >> 6, dd = cc & 63;
                int bidx = m >> 11;
                int l = m & 2047;
                size_t i0 = (((size_t)(bidx * H_ + h)) * L_ + l) * DH_ + dd;
                size_t i1 = (((size_t)(bidx * H_ + h)) * L_ + l + 8) * DH_ + dd;
                if (mat == 0) {
                    *(float2*)(g_q + i0) = v0;
                    *(float2*)(g_q + i1) = v1;
                } else if (mat == 1) {
                    *(float2*)(g_k + i0) = v0;
                    *(float2*)(g_k + i1) = v1;
                } else {
                    *(float2*)(g_v + i0) = make_float2(tf32rna(v0.x), tf32rna(v0.y));
                    *(float2*)(g_v + i1) = make_float2(tf32rna(v1.x), tf32rna(v1.y));
                }
            }
        }
    }
}

// ---------------------------------------------------------------------------
// Attention, tensor-pipe, double-buffered K/V tiles (alignment-clean:
// 68-float rows = 272 B = 17*16).
// 128 q-rows/CTA, 64-key tiles, 8 warps; warp tile 16 rows x 64 keys.
//  - K fp32 in smem, split to tf32 hi/lo in regs at B-fragment load
//  - scores 3xTF32; exp+rowsum in frag layout; e -> gmem fp32
//  - C-frag -> AV A-frag via quad shuffles; AV mma with V (tf32)
//  - epilogue: hout pre-split; fused rescale of attn rows
// smem: sq[128][68] + 2 x (K[64][68] + V[64][68]) + srow[128]
//       = 8704 + 17408 + 128 floats = 104960 B -> occ 2
// ---------------------------------------------------------------------------
#define SQ_F (128 * 68)
#define TK_F (64 * 68)
#define ATTN_SMEM_FLOATS (SQ_F + 4 * TK_F + 128)
#define ATTN_SMEM_BYTES  (ATTN_SMEM_FLOATS * 4)   // 104960

__global__ __launch_bounds__(256, 2) void attn_kernel(float* __restrict__ attn_out)
{
    extern __shared__ float sm[];
    float* sq   = sm;                       // [row][d] stride 68 fp32
    float* srow = sm + SQ_F + 4 * TK_F;     // [128]
    const uint32_t sb = smem_u32(sm);

    const int tid = threadIdx.x;
    const int wid = tid >> 5;
    const int lane = tid & 31;
    const int grp = lane >> 2;
    const int tg = lane & 3;
    const int mr = wid * 16 + grp;

    const int bh = blockIdx.y;
    const int q0 = blockIdx.x * 128;
    const size_t base = (size_t)bh * L_ * DH_;
    float* attn = attn_out + (size_t)bh * L_ * L_;

    const int klr = tid >> 2;          // 0..63 key row
    const int kc = (tid & 3) * 16;     // col group (16 floats = 64 B aligned)

    auto load_tile = [&](int kt) {
        if (kt < L_ / 64) {
            int s = kt & 1;
            const float* pk = g_k + base + (size_t)(kt * 64 + klr) * DH_ + kc;
            const float* pv = g_v + base + (size_t)(kt * 64 + klr) * DH_ + kc;
            uint32_t dk = sb + (SQ_F + s * 2 * TK_F + klr * 68 + kc) * 4;
            uint32_t dv = dk + TK_F * 4;
#pragma unroll
            for (int j = 0; j < 4; j++) {
                cpa16(dk + j * 16, pk + j * 4);
                cpa16(dv + j * 16, pv + j * 4);
            }
        }
        asm volatile("cp.async.commit_group;" ::: "memory");
    };

    // Q tile load (one-time, group 0) then tile-0 prefetch (group 1)
    {
        int lr = tid >> 1;
        int lc = (tid & 1) * 32;
        const float* src = g_q + base + (size_t)(q0 + lr) * DH_ + lc;
        uint32_t dst = sb + (lr * 68 + lc) * 4;
#pragma unroll
        for (int j = 0; j < 8; j++) cpa16(dst + j * 16, src + j * 4);
        asm volatile("cp.async.commit_group;" ::: "memory");
    }
    load_tile(0);

    float o[8][4];
#pragma unroll
    for (int j = 0; j < 8; j++)
#pragma unroll
        for (int e = 0; e < 4; e++) o[j][e] = 0.f;
    float rsum0 = 0.f, rsum1 = 0.f;

    for (int kt = 0; kt < L_ / 64; kt++) {
        const int k0g = kt * 64;
        load_tile(kt + 1);
        asm volatile("cp.async.wait_group 1;" ::: "memory");
        __syncthreads();

        const int s = kt & 1;
        const float* sK = sm + SQ_F + s * 2 * TK_F;
        const float* sV = sK + TK_F;

        // ---- scores: 3xTF32 mma; Q and K split to hi/lo in regs ----
        float c[8][4];
#pragma unroll
        for (int nf = 0; nf < 8; nf++)
#pragma unroll
            for (int e = 0; e < 4; e++) c[nf][e] = 0.f;

#pragma unroll
        for (int k8 = 0; k8 < 8; k8++) {
            const int kk = k8 * 8;
            float af[4], aH[4], aL[4];
            af[0] = sq[(mr) * 68 + kk + tg];
            af[1] = sq[(mr + 8) * 68 + kk + tg];
            af[2] = sq[(mr) * 68 + kk + tg + 4];
            af[3] = sq[(mr + 8) * 68 + kk + tg + 4];
#pragma unroll
            for (int e = 0; e < 4; e++) {
                aH[e] = tf32rna(af[e]);
                aL[e] = tf32rna(af[e] - aH[e]);
            }
#pragma unroll
            for (int nf = 0; nf < 8; nf++) {
                int nr = nf * 8 + grp;
                float bf0 = sK[nr * 68 + kk + tg];
                float bf1 = sK[nr * 68 + kk + tg + 4];
                float bH[2], bL[2];
                bH[0] = tf32rna(bf0); bL[0] = tf32rna(bf0 - bH[0]);
                bH[1] = tf32rna(bf1); bL[1] = tf32rna(bf1 - bH[1]);
                mma8(c[nf], aH, bH);
                mma8(c[nf], aL, bH);
                mma8(c[nf], aH, bL);
            }
        }

        // ---- exp + rowsum + gmem store (fragment layout) ----
        {
            float rs0 = 0.f, rs1 = 0.f;
#pragma unroll
            for (int nf = 0; nf < 8; nf++) {
                float e0 = __expf(c[nf][0] * 0.125f);
                float e1 = __expf(c[nf][1] * 0.125f);
                float e2 = __expf(c[nf][2] * 0.125f);
                float e3 = __expf(c[nf][3] * 0.125f);
                c[nf][0] = e0; c[nf][1] = e1; c[nf][2] = e2; c[nf][3] = e3;
                rs0 += e0 + e1;
                rs1 += e2 + e3;
                int n = k0g + nf * 8 + tg * 2;
                *(float2*)(attn + (size_t)(q0 + mr) * L_ + n) = make_float2(e0, e1);
                *(float2*)(attn + (size_t)(q0 + mr + 8) * L_ + n) = make_float2(e2, e3);
            }
            rs0 += __shfl_xor_sync(0xffffffffu, rs0, 1);
            rs0 += __shfl_xor_sync(0xffffffffu, rs0, 2);
            rs1 += __shfl_xor_sync(0xffffffffu, rs1, 1);
            rs1 += __shfl_xor_sync(0xffffffffu, rs1, 2);
            rsum0 += rs0;
            rsum1 += rs1;
        }

        // ---- AV: C-frag -> A-frag via quad shuffles, mma with V ----
        const int s1 = (lane & ~3) | (tg >> 1);
        const int s2 = s1 + 2;
        const bool odd = tg & 1;
#pragma unroll
        for (int nf = 0; nf < 8; nf++) {
            float v0 = __shfl_sync(0xffffffffu, c[nf][0], s1);
            float v1 = __shfl_sync(0xffffffffu, c[nf][1], s1);
            float v2 = __shfl_sync(0xffffffffu, c[nf][2], s1);
            float v3 = __shfl_sync(0xffffffffu, c[nf][3], s1);
            float w0 = __shfl_sync(0xffffffffu, c[nf][0], s2);
            float w1 = __shfl_sync(0xffffffffu, c[nf][1], s2);
            float w2 = __shfl_sync(0xffffffffu, c[nf][2], s2);
            float w3 = __shfl_sync(0xffffffffu, c[nf][3], s2);
            float a[4];
            a[0] = tf32rna(odd ? v1 : v0);
            a[1] = tf32rna(odd ? v3 : v2);
            a[2] = tf32rna(odd ? w1 : w0);
            a[3] = tf32rna(odd ? w3 : w2);
            const int kk = nf * 8;
#pragma unroll
            for (int j = 0; j < 8; j++) {
                float b[2];
                b[0] = sV[(kk + tg) * 68 + j * 8 + grp];
                b[1] = sV[(kk + tg + 4) * 68 + j * 8 + grp];
                mma8(o[j], a, b);
            }
        }
        __syncthreads();   // stage consumed; next iter may overwrite it
    }

    if (tg == 0) {
        srow[wid * 16 + grp] = rsum0;
        srow[wid * 16 + grp + 8] = rsum1;
    }
    __syncthreads();

    const int bidx = bh >> 4;
    const int h = bh & 15;

    // O epilogue: normalize + tf32split -> g_hhi/g_hlo
    {
        float i0 = 1.f / srow[wid * 16 + grp];
        float i1 = 1.f / srow[wid * 16 + grp + 8];
        size_t r0 = ((size_t)(bidx * L_) + q0 + mr) * DM_ + h * DH_;
        size_t r1 = r0 + (size_t)8 * DM_;
#pragma unroll
        for (int j = 0; j < 8; j++) {
            int nd = j * 8 + tg * 2;
            float2 sx = tf32split(o[j][0] * i0);
            float2 sy = tf32split(o[j][1] * i0);
            *(float2*)(g_hhi + r0 + nd) = make_float2(sx.x, sy.x);
            *(float2*)(g_hlo + r0 + nd) = make_float2(sx.y, sy.y);
            sx = tf32split(o[j][2] * i1);
            sy = tf32split(o[j][3] * i1);
            *(float2*)(g_hhi + r1 + nd) = make_float2(sx.x, sy.x);
            *(float2*)(g_hlo + r1 + nd) = make_float2(sx.y, sy.y);
        }
    }

    // fused rescale of this CTA's 128 attn rows
    {
        const int ty = tid >> 4;
        const int tx = tid & 15;
#pragma unroll
        for (int i = 0; i < 8; i++) {
            float inv = 1.f / srow[ty * 8 + i];
            float* rowp = attn + (size_t)(q0 + ty * 8 + i) * L_;
#pragma unroll 4
            for (int j = 0; j < 32; j++) {
                float4* p = (float4*)(rowp + j * 64 + tx * 4);
                float4 v = *p;
                v.x *= inv; v.y *= inv; v.z *= inv; v.w *= inv;
                *p = v;
            }
        }
    }
}

// ---------------------------------------------------------------------------
extern "C" void kernel_launch(void* const* d_in, const int* in_sizes, int n_in,
                              void* d_out, int out_size)
{
    (void)in_sizes; (void)n_in; (void)out_size;
    const float* x    = (const float*)d_in[0];
    const float* Wqkv = (const float*)d_in[1];
    const float* bqkv = (const float*)d_in[2];
    const float* Wout = (const float*)d_in[3];
    const float* bout = (const float*)d_in[4];
    float* out  = (float*)d_out;
    float* attn = out + OUT_ELEMS_;

    static int attr_done = 0;
    if (!attr_done) {
        cudaFuncSetAttribute(attn_kernel,
            cudaFuncAttributeMaxDynamicSharedMemorySize, ATTN_SMEM_BYTES);
        cudaFuncSetAttribute(gemm_mma_kernel<0>,
            cudaFuncAttributeMaxDynamicSharedMemorySize, GEMM_SMEM_BYTES);
        cudaFuncSetAttribute(gemm_mma_kernel<1>,
            cudaFuncAttributeMaxDynamicSharedMemorySize, GEMM_SMEM_BYTES);
        attr_done = 1;
    }

    float *xhi, *xlo, *wqhi, *wqlo, *wohi, *wolo, *hhi, *hlo;
    cudaGetSymbolAddress((void**)&xhi,  g_xhi);
    cudaGetSymbolAddress((void**)&xlo,  g_xlo);
    cudaGetSymbolAddress((void**)&wqhi, g_wqhi);
    cudaGetSymbolAddress((void**)&wqlo, g_wqlo);
    cudaGetSymbolAddress((void**)&wohi, g_wohi);
    cudaGetSymbolAddress((void**)&wolo, g_wolo);
    cudaGetSymbolAddress((void**)&hhi,  g_hhi);
    cudaGetSymbolAddress((void**)&hlo,  g_hlo);

    // operand decompositions
    decomp_kernel<<<OUT_ELEMS_ / 4 / 256, 256>>>(x, xhi, xlo);
    decomp_t_kernel<<<dim3(N3_ / 32, DM_ / 32), 256>>>(Wqkv, wqhi, wqlo, DM_, N3_);
    decomp_t_kernel<<<dim3(DM_ / 32, DM_ / 32), 256>>>(Wout, wohi, wolo, DM_, DM_);

    // QKV projection (q,k fp32; v tf32-rounded)
    gemm_mma_kernel<1><<<dim3(N3_ / 128, (B_ * L_) / 128), 256, GEMM_SMEM_BYTES>>>(
        xhi, xlo, wqhi, wqlo, bqkv, nullptr);

    // attention (double-buffered, scores + AV on tensor pipe) + fused rescale
    attn_kernel<<<dim3(L_ / 128, BH_), 256, ATTN_SMEM_BYTES>>>(attn);

    // out projection (reads pre-split hhi/hlo straight from attn)
    gemm_mma_kernel<0><<<dim3(DM_ / 128, (B_ * L_) / 128), 256, GEMM_SMEM_BYTES>>>(
        hhi, hlo, wohi, wolo, bout, out);
}